// round 12
// baseline (speedup 1.0000x reference)
#include <cuda_runtime.h>
#include <cuda_bf16.h>
#include <cuda_fp16.h>
#include <cstdint>

// ---------------------------------------------------------------------------
// MultiHeadAreaAttention. Precision-tiered tensor-core pipeline:
//   Q/K chain (proj Q, proj K, QK^T): split-bf16 3-term (needs ~1e-4 logits)
//   V path (proj V, G@V, out proj):   single-term fp16 (tolerates ~1e-4 rel)
// Round 11: resubmit of R10 (8-warp 128x256 GEMM tiles, single-wave grids);
// R10 bench was an infra flake (same signature as R6, which passed as R7).
// ---------------------------------------------------------------------------

#define BH_ 128
#define L_  512
typedef __nv_bfloat16 bf16;

// bf16 split operands for Q/K chain
__device__ bf16 g_Aq[(size_t)8192 * 1024];
__device__ bf16 g_Ak[(size_t)8192 * 1024];
__device__ bf16 g_Bq[512 * 1024];
__device__ bf16 g_Bk[512 * 1024];
__device__ bf16 g_Qs[(size_t)BH_ * 512 * 128];  // [bh][l][hi64|lo64]
__device__ bf16 g_Ks[(size_t)BH_ * 512 * 128];

// fp16 single operands for V path
__device__ __half g_Avh[(size_t)8192 * 512];     // fp16(v)
__device__ __half g_Bvh[512 * 512];              // fp16(Wv)^T  (n-major)
__device__ __half g_Boh[512 * 512];              // fp16(Wo)^T
__device__ __half g_Vth[(size_t)BH_ * 64 * 512]; // V^T per bh
__device__ __half g_Gh[(size_t)BH_ * 512 * 512]; // softmax-folded G
__device__ __half g_Aath[(size_t)8192 * 512];    // attn rows [b*512+t][h*64+d]

__device__ float g_Vh[(size_t)BH_ * 512 * 64];   // fp32 V heads (proj V out)
__device__ float g_S[(size_t)BH_ * 512 * 512];   // scores fp32

// ---------------------------------------------------------------------------
static __device__ __forceinline__ uint32_t smem_u32(const void* p) {
    uint32_t a;
    asm("{ .reg .u64 t; cvta.to.shared.u64 t, %1; cvt.u32.u64 %0, t; }"
        : "=r"(a) : "l"(p));
    return a;
}
static __device__ __forceinline__ void ldsm4(uint32_t* r, uint32_t a) {
    asm volatile("ldmatrix.sync.aligned.m8n8.x4.shared.b16 {%0,%1,%2,%3}, [%4];"
                 : "=r"(r[0]), "=r"(r[1]), "=r"(r[2]), "=r"(r[3]) : "r"(a));
}
static __device__ __forceinline__ void mma_bf16(float* d, const uint32_t* a,
                                                uint32_t b0, uint32_t b1) {
    asm volatile(
        "mma.sync.aligned.m16n8k16.row.col.f32.bf16.bf16.f32 "
        "{%0,%1,%2,%3},{%4,%5,%6,%7},{%8,%9},{%0,%1,%2,%3};"
        : "+f"(d[0]), "+f"(d[1]), "+f"(d[2]), "+f"(d[3])
        : "r"(a[0]), "r"(a[1]), "r"(a[2]), "r"(a[3]), "r"(b0), "r"(b1));
}
static __device__ __forceinline__ void mma_f16(float* d, const uint32_t* a,
                                               uint32_t b0, uint32_t b1) {
    asm volatile(
        "mma.sync.aligned.m16n8k16.row.col.f32.f16.f16.f32 "
        "{%0,%1,%2,%3},{%4,%5,%6,%7},{%8,%9},{%0,%1,%2,%3};"
        : "+f"(d[0]), "+f"(d[1]), "+f"(d[2]), "+f"(d[3])
        : "r"(a[0]), "r"(a[1]), "r"(a[2]), "r"(a[3]), "r"(b0), "r"(b1));
}
#define CP16(dst, src)                                                         \
    asm volatile("cp.async.cg.shared.global [%0], [%1], 16;" ::"r"(dst),       \
                 "l"(src))
#define CP_COMMIT() asm volatile("cp.async.commit_group;")
#define CP_WAIT(n) asm volatile("cp.async.wait_group %0;" ::"n"(n))

// ---------------------------------------------------------------------------
// conversions
// ---------------------------------------------------------------------------
__global__ __launch_bounds__(256) void convX_all(const float* __restrict__ q,
                                                 const float* __restrict__ k)
{
    int z = blockIdx.z;
    const float* X = (z == 0) ? q : k;
    bf16* A = (z == 0) ? g_Aq : g_Ak;
    size_t i4 = (size_t)blockIdx.x * 256 + threadIdx.x;
    size_t r = i4 >> 7;
    int kq = (int)(i4 & 127) * 4;
    float4 x = *(const float4*)(X + r * 512 + kq);
    bf16 h0 = __float2bfloat16(x.x), h1 = __float2bfloat16(x.y);
    bf16 h2 = __float2bfloat16(x.z), h3 = __float2bfloat16(x.w);
    bf16 l0 = __float2bfloat16(x.x - __bfloat162float(h0));
    bf16 l1 = __float2bfloat16(x.y - __bfloat162float(h1));
    bf16 l2 = __float2bfloat16(x.z - __bfloat162float(h2));
    bf16 l3 = __float2bfloat16(x.w - __bfloat162float(h3));
    __nv_bfloat162* p0 = (__nv_bfloat162*)(A + r * 1024 + kq);
    __nv_bfloat162* p1 = (__nv_bfloat162*)(A + r * 1024 + 512 + kq);
    p0[0] = __halves2bfloat162(h0, h1);
    p0[1] = __halves2bfloat162(h2, h3);
    p1[0] = __halves2bfloat162(l0, l1);
    p1[1] = __halves2bfloat162(l2, l3);
}

__global__ __launch_bounds__(256) void convV_h(const float* __restrict__ v)
{
    size_t idx = (size_t)blockIdx.x * 256 + threadIdx.x;
    float4 x = ((const float4*)v)[idx];
    __half2* p = (__half2*)(g_Avh + idx * 4);
    p[0] = __floats2half2_rn(x.x, x.y);
    p[1] = __floats2half2_rn(x.z, x.w);
}

__global__ __launch_bounds__(256) void convW_all(const float* __restrict__ Wq,
                                                 const float* __restrict__ Wk)
{
    __shared__ float t[32][33];
    int z = blockIdx.z;
    const float* W = (z == 0) ? Wq : Wk;
    bf16* Bp = (z == 0) ? g_Bq : g_Bk;
    int n0 = blockIdx.x * 32, k0 = blockIdx.y * 32;
    int tx = threadIdx.x & 31, ty = threadIdx.x >> 5;
#pragma unroll
    for (int i = 0; i < 4; i++)
        t[ty + i * 8][tx] = W[(size_t)(k0 + ty + i * 8) * 512 + n0 + tx];
    __syncthreads();
#pragma unroll
    for (int i = 0; i < 4; i++) {
        int n = n0 + ty + i * 8, k = k0 + tx;
        float w = t[tx][ty + i * 8];
        bf16 h = __float2bfloat16(w);
        bf16 l = __float2bfloat16(w - __bfloat162float(h));
        Bp[(size_t)n * 1024 + k]       = h;
        Bp[(size_t)n * 1024 + 512 + k] = l;
    }
}

__global__ __launch_bounds__(256) void convW_h(const float* __restrict__ Wv,
                                               const float* __restrict__ Wo)
{
    __shared__ float t[32][33];
    int z = blockIdx.z;
    const float* W = (z == 0) ? Wv : Wo;
    __half* Bp = (z == 0) ? g_Bvh : g_Boh;
    int n0 = blockIdx.x * 32, k0 = blockIdx.y * 32;
    int tx = threadIdx.x & 31, ty = threadIdx.x >> 5;
#pragma unroll
    for (int i = 0; i < 4; i++)
        t[ty + i * 8][tx] = W[(size_t)(k0 + ty + i * 8) * 512 + n0 + tx];
    __syncthreads();
#pragma unroll
    for (int i = 0; i < 4; i++) {
        int n = n0 + ty + i * 8, k = k0 + tx;
        Bp[(size_t)n * 512 + k] = __float2half(t[tx][ty + i * 8]);
    }
}

// ---------------------------------------------------------------------------
// bf16 3-term dense GEMM (Q/K projections).
// 256 threads / 8 warps (2x4), block tile 128x256, warp tile 64x64, BK=32.
// Stage: A hi(10240) A lo(10240) B hi(20480) B lo(20480) = 61440; 2 stages.
// ---------------------------------------------------------------------------
#define PANEL 10240
#define BPANEL 20480
#define DSTAGE 61440
#define DSMEM 122880

template <int MODE>  // 0: Q proj -> g_Qs ; 1: K proj -> g_Ks
__global__ __launch_bounds__(256) void mma_gemm(const float* __restrict__ bias)
{
    const bf16* A  = (MODE == 0) ? g_Aq : g_Ak;
    const bf16* Bp = (MODE == 0) ? g_Bq : g_Bk;
    extern __shared__ char sm[];
    uint32_t sb = smem_u32(sm);
    const int tid = threadIdx.x, lane = tid & 31, wid = tid >> 5;
    const int wy = wid >> 2, wx = wid & 3;
    const int row0 = blockIdx.y * 128, col0 = blockIdx.x * 256;

    const uint32_t aOff = ((wy * 64 + (lane & 15)) * 40 + ((lane >> 4) << 3)) * 2;
    const uint32_t bOff =
        ((wx * 64 + ((lane >> 4) << 3) + (lane & 7)) * 40 + (lane & 8)) * 2;

    float acc[4][8][4];
#pragma unroll
    for (int i = 0; i < 4; i++)
#pragma unroll
        for (int j = 0; j < 8; j++)
#pragma unroll
            for (int q = 0; q < 4; q++) acc[i][j][q] = 0.f;

#define FILL_D(kk, st)                                                          \
    {                                                                           \
        uint32_t stb = sb + (st)*DSTAGE;                                        \
        _Pragma("unroll") for (int i = 0; i < 2; i++)                           \
        {                                                                       \
            int s = tid + i * 256;                                              \
            int r = s >> 2, c = s & 3;                                          \
            uint32_t off = (uint32_t)(r * 40 + c * 8) * 2;                      \
            const bf16* a0 = A + (size_t)(row0 + r) * 1024 + (kk)*32 + c * 8;   \
            CP16(stb + off, a0);                                                \
            CP16(stb + PANEL + off, a0 + 512);                                  \
        }                                                                       \
        _Pragma("unroll") for (int i = 0; i < 4; i++)                           \
        {                                                                       \
            int s = tid + i * 256;                                              \
            int r = s >> 2, c = s & 3;                                          \
            uint32_t off = (uint32_t)(r * 40 + c * 8) * 2;                      \
            const bf16* b0 = Bp + (size_t)(col0 + r) * 1024 + (kk)*32 + c * 8;  \
            CP16(stb + 2 * PANEL + off, b0);                                    \
            CP16(stb + 2 * PANEL + BPANEL + off, b0 + 512);                     \
        }                                                                       \
        CP_COMMIT();                                                            \
    }

    FILL_D(0, 0);
    FILL_D(1, 1);
    for (int kk = 0; kk < 16; kk++) {
        if (kk < 15) CP_WAIT(1); else CP_WAIT(0);
        __syncthreads();
        uint32_t stb = sb + (kk & 1) * DSTAGE;
#pragma unroll
        for (int ks = 0; ks < 2; ks++) {
            uint32_t ah[4][4], al[4][4], bh[4][4], bl[4][4];
#pragma unroll
            for (int mi = 0; mi < 4; mi++) {
                ldsm4(ah[mi], stb + aOff + mi * 1280 + ks * 32);
                ldsm4(al[mi], stb + PANEL + aOff + mi * 1280 + ks * 32);
            }
#pragma unroll
            for (int ng = 0; ng < 4; ng++) {
                ldsm4(bh[ng], stb + 2 * PANEL + bOff + ng * 1280 + ks * 32);
                ldsm4(bl[ng], stb + 2 * PANEL + BPANEL + bOff + ng * 1280 + ks * 32);
            }
#pragma unroll
            for (int mi = 0; mi < 4; mi++)
#pragma unroll
                for (int ni = 0; ni < 8; ni++) {
                    uint32_t bh0 = bh[ni >> 1][(ni & 1) * 2];
                    uint32_t bh1 = bh[ni >> 1][(ni & 1) * 2 + 1];
                    mma_bf16(acc[mi][ni], ah[mi], bh0, bh1);
                    mma_bf16(acc[mi][ni], al[mi], bh0, bh1);
                    mma_bf16(acc[mi][ni], ah[mi],
                             bl[ni >> 1][(ni & 1) * 2],
                             bl[ni >> 1][(ni & 1) * 2 + 1]);
                }
        }
        __syncthreads();
        if (kk + 2 < 16) FILL_D(kk + 2, kk & 1);
    }

#pragma unroll
    for (int mi = 0; mi < 4; mi++)
#pragma unroll
        for (int ni = 0; ni < 8; ni++) {
            int r0 = row0 + wy * 64 + mi * 16 + (lane >> 2);
            int cc = col0 + wx * 64 + ni * 8 + (lane & 3) * 2;
            float b0 = __ldg(&bias[cc]), b1 = __ldg(&bias[cc + 1]);
#pragma unroll
            for (int half = 0; half < 2; half++) {
                int r = r0 + half * 8;
                float v0 = acc[mi][ni][half * 2] + b0;
                float v1 = acc[mi][ni][half * 2 + 1] + b1;
                int bh = ((r >> 9) << 3) + (cc >> 6), l = r & 511, d = cc & 63;
                bf16 h0 = __float2bfloat16(v0), h1 = __float2bfloat16(v1);
                bf16 l0 = __float2bfloat16(v0 - __bfloat162float(h0));
                bf16 l1 = __float2bfloat16(v1 - __bfloat162float(h1));
                bf16* dst =
                    ((MODE == 0) ? g_Qs : g_Ks) + ((size_t)bh * 512 + l) * 128 + d;
                *(__nv_bfloat162*)dst        = __halves2bfloat162(h0, h1);
                *(__nv_bfloat162*)(dst + 64) = __halves2bfloat162(l0, l1);
            }
        }
}

// ---------------------------------------------------------------------------
// fp16 single-term dense GEMM. 256 threads / 8 warps (2x4), tile 128x256.
// BK=64 as two k32 sub-panels. Stage layout mirrors the bf16 kernel.
// MODE 0: V proj -> g_Vh fp32 head-split (+bv); MODE 1: out -> Y (+bo)
// ---------------------------------------------------------------------------
template <int MODE>
__global__ __launch_bounds__(256) void gemm_h(const float* __restrict__ bias,
                                              float* __restrict__ Y)
{
    const __half* A = (MODE == 0) ? g_Avh : g_Aath;
    const __half* B = (MODE == 0) ? g_Bvh : g_Boh;
    extern __shared__ char sm[];
    uint32_t sb = smem_u32(sm);
    const int tid = threadIdx.x, lane = tid & 31, wid = tid >> 5;
    const int wy = wid >> 2, wx = wid & 3;
    const int row0 = blockIdx.y * 128, col0 = blockIdx.x * 256;

    const uint32_t aOff = ((wy * 64 + (lane & 15)) * 40 + ((lane >> 4) << 3)) * 2;
    const uint32_t bOff =
        ((wx * 64 + ((lane >> 4) << 3) + (lane & 7)) * 40 + (lane & 8)) * 2;

    float acc[4][8][4];
#pragma unroll
    for (int i = 0; i < 4; i++)
#pragma unroll
        for (int j = 0; j < 8; j++)
#pragma unroll
            for (int q = 0; q < 4; q++) acc[i][j][q] = 0.f;

#define FILL_H(kk, st)                                                          \
    {                                                                           \
        uint32_t stb = sb + (st)*DSTAGE;                                        \
        _Pragma("unroll") for (int i = 0; i < 2; i++)                           \
        {                                                                       \
            int s = tid + i * 256;                                              \
            int r = s >> 2, c = s & 3;                                          \
            uint32_t off = (uint32_t)(r * 40 + c * 8) * 2;                      \
            const __half* a0 = A + (size_t)(row0 + r) * 512 + (kk)*64 + c * 8;  \
            CP16(stb + off, a0);                                                \
            CP16(stb + PANEL + off, a0 + 32);                                   \
        }                                                                       \
        _Pragma("unroll") for (int i = 0; i < 4; i++)                           \
        {                                                                       \
            int s = tid + i * 256;                                              \
            int r = s >> 2, c = s & 3;                                          \
            uint32_t off = (uint32_t)(r * 40 + c * 8) * 2;                      \
            const __half* b0 = B + (size_t)(col0 + r) * 512 + (kk)*64 + c * 8;  \
            CP16(stb + 2 * PANEL + off, b0);                                    \
            CP16(stb + 2 * PANEL + BPANEL + off, b0 + 32);                      \
        }                                                                       \
        CP_COMMIT();                                                            \
    }

    FILL_H(0, 0);
    FILL_H(1, 1);
    for (int kk = 0; kk < 8; kk++) {
        if (kk < 7) CP_WAIT(1); else CP_WAIT(0);
        __syncthreads();
        uint32_t stb = sb + (kk & 1) * DSTAGE;
#pragma unroll
        for (int sub = 0; sub < 2; sub++) {
            uint32_t ap = stb + sub * PANEL;
            uint32_t bp = stb + 2 * PANEL + sub * BPANEL;
#pragma unroll
            for (int ks = 0; ks < 2; ks++) {
                uint32_t af[4][4], bfr[4][4];
#pragma unroll
                for (int mi = 0; mi < 4; mi++)
                    ldsm4(af[mi], ap + aOff + mi * 1280 + ks * 32);
#pragma unroll
                for (int ng = 0; ng < 4; ng++)
                    ldsm4(bfr[ng], bp + bOff + ng * 1280 + ks * 32);
#pragma unroll
                for (int mi = 0; mi < 4; mi++)
#pragma unroll
                    for (int ni = 0; ni < 8; ni++)
                        mma_f16(acc[mi][ni], af[mi],
                                bfr[ni >> 1][(ni & 1) * 2],
                                bfr[ni >> 1][(ni & 1) * 2 + 1]);
            }
        }
        __syncthreads();
        if (kk + 2 < 8) FILL_H(kk + 2, kk & 1);
    }

#pragma unroll
    for (int mi = 0; mi < 4; mi++)
#pragma unroll
        for (int ni = 0; ni < 8; ni++) {
            int r0 = row0 + wy * 64 + mi * 16 + (lane >> 2);
            int cc = col0 + wx * 64 + ni * 8 + (lane & 3) * 2;
            float b0 = __ldg(&bias[cc]), b1 = __ldg(&bias[cc + 1]);
#pragma unroll
            for (int half = 0; half < 2; half++) {
                int r = r0 + half * 8;
                float v0 = acc[mi][ni][half * 2] + b0;
                float v1 = acc[mi][ni][half * 2 + 1] + b1;
                if (MODE == 1) {
                    *(float2*)(Y + (size_t)r * 512 + cc) = make_float2(v0, v1);
                } else {
                    int bh = ((r >> 9) << 3) + (cc >> 6), l = r & 511, d = cc & 63;
                    *(float2*)(g_Vh + ((size_t)bh * 512 + l) * 64 + d) =
                        make_float2(v0, v1);
                }
            }
        }
}

// ---------------------------------------------------------------------------
// V transpose: g_Vh [bh][512][64] fp32 -> g_Vth [bh][64][512] fp16
// ---------------------------------------------------------------------------
__global__ __launch_bounds__(256) void vtrans()
{
    int l0 = blockIdx.x * 64, bh = blockIdx.y;
    __shared__ float sm[64][68];
    const float* V = g_Vh + (size_t)bh * 512 * 64;
    int tid = threadIdx.x;
#pragma unroll
    for (int i = 0; i < 4; i++) {
        int idx4 = tid + i * 256;
        int r = idx4 >> 4, c4 = (idx4 & 15) * 4;
        *(float4*)&sm[r][c4] = *(const float4*)(V + (size_t)(l0 + r) * 64 + c4);
    }
    __syncthreads();
    __half* O = g_Vth + (size_t)bh * 64 * 512;
#pragma unroll
    for (int i = 0; i < 16; i++) {
        int e = tid + i * 256;
        int d = e >> 6, l = e & 63;
        O[(size_t)d * 512 + l0 + l] = __float2half(sm[l][d]);
    }
}

// ---------------------------------------------------------------------------
// qk: S = Qs @ Ks^T per bh (bf16 3-term). 256 threads / 8 warps (2 my x 4 nx),
// warp tile 64x32, whole split-K resident (8 panels x 10240 = 81920).
// ---------------------------------------------------------------------------
__global__ __launch_bounds__(256) void qk_mma()
{
    int tk = blockIdx.x, tq = blockIdx.y, bh = blockIdx.z;
    if (tk > tq) return;
    const bf16* Aq = g_Qs + (size_t)bh * 512 * 128;
    const bf16* Bk = g_Ks + (size_t)bh * 512 * 128;
    extern __shared__ char sm[];
    uint32_t sb = smem_u32(sm);
    const int tid = threadIdx.x, lane = tid & 31, wid = tid >> 5;
    const int wy = wid >> 2, wx = wid & 3;
    const int row0 = tq * 128, col0 = tk * 128;

    const uint32_t aOff = ((wy * 64 + (lane & 15)) * 40 + ((lane >> 4) << 3)) * 2;
    const uint32_t bOff =
        ((wx * 32 + ((lane >> 4) << 3) + (lane & 7)) * 40 + (lane & 8)) * 2;

#pragma unroll
    for (int p = 0; p < 4; p++) {  // p = part*2 + kchunk
        int part = p >> 1, kk = p & 1;
        int colb = part * 64 + kk * 32;
#pragma unroll
        for (int i = 0; i < 2; i++) {
            int s = tid + i * 256;
            int r = s >> 2, c = s & 3;
            uint32_t off = (uint32_t)(r * 40 + c * 8) * 2;
            CP16(sb + p * PANEL + off,
                 Aq + (size_t)(row0 + r) * 128 + colb + c * 8);
            CP16(sb + (4 + p) * PANEL + off,
                 Bk + (size_t)(col0 + r) * 128 + colb + c * 8);
        }
    }
    CP_COMMIT();

    float acc[4][4][4];
#pragma unroll
    for (int i = 0; i < 4; i++)
#pragma unroll
        for (int j = 0; j < 4; j++)
#pragma unroll
            for (int q = 0; q < 4; q++) acc[i][j][q] = 0.f;

    CP_WAIT(0);
    __syncthreads();

#pragma unroll
    for (int kk = 0; kk < 2; kk++) {
        uint32_t qh = sb + kk * PANEL, ql = sb + (2 + kk) * PANEL;
        uint32_t kh = sb + (4 + kk) * PANEL, kl = sb + (6 + kk) * PANEL;
#pragma unroll
        for (int ks = 0; ks < 2; ks++) {
            uint32_t ah[4][4], al[4][4], bh[2][4], bl[2][4];
#pragma unroll
            for (int mi = 0; mi < 4; mi++) {
                ldsm4(ah[mi], qh + aOff + mi * 1280 + ks * 32);
                ldsm4(al[mi], ql + aOff + mi * 1280 + ks * 32);
            }
#pragma unroll
            for (int ng = 0; ng < 2; ng++) {
                ldsm4(bh[ng], kh + bOff + ng * 1280 + ks * 32);
                ldsm4(bl[ng], kl + bOff + ng * 1280 + ks * 32);
            }
#pragma unroll
            for (int mi = 0; mi < 4; mi++)
#pragma unroll
                for (int ni = 0; ni < 4; ni++) {
                    uint32_t bh0 = bh[ni >> 1][(ni & 1) * 2];
                    uint32_t bh1 = bh[ni >> 1][(ni & 1) * 2 + 1];
                    mma_bf16(acc[mi][ni], ah[mi], bh0, bh1);
                    mma_bf16(acc[mi][ni], al[mi], bh0, bh1);
                    mma_bf16(acc[mi][ni], ah[mi],
                             bl[ni >> 1][(ni & 1) * 2],
                             bl[ni >> 1][(ni & 1) * 2 + 1]);
                }
        }
    }

    float* Smat = g_S + (size_t)bh * 512 * 512;
#pragma unroll
    for (int mi = 0; mi < 4; mi++)
#pragma unroll
        for (int ni = 0; ni < 4; ni++) {
            int r = row0 + wy * 64 + mi * 16 + (lane >> 2);
            int cc = col0 + wx * 32 + ni * 8 + (lane & 3) * 2;
            *(float2*)(Smat + (size_t)r * 512 + cc) =
                make_float2(acc[mi][ni][0], acc[mi][ni][1]);
            *(float2*)(Smat + (size_t)(r + 8) * 512 + cc) =
                make_float2(acc[mi][ni][2], acc[mi][ni][3]);
        }
}

// ---------------------------------------------------------------------------
// Per-row cumsum + area softmax + fold; emits G fp16 up to tile bound.
// ---------------------------------------------------------------------------
__global__ __launch_bounds__(128) void area_softmax_kernel()
{
    __shared__ float Cb[4][516];
    __shared__ float Tb[4][516];
    __shared__ float Ub[4][516];
    __shared__ float Vb[4][516];

    int wrp = threadIdx.x >> 5;
    int lane = threadIdx.x & 31;
    int t = blockIdx.x * 4 + wrp;
    int bh = blockIdx.y;
    int bound = ((t >> 7) + 1) << 7;  // av reads j < bound only

    const float* Srow = g_S + ((size_t)bh * L_ + t) * L_;
    __half* Grow = g_Gh + ((size_t)bh * L_ + t) * 512;
    float* C = Cb[wrp];
    float* T = Tb[wrp];
    float* U = Ub[wrp];
    float* V = Vb[wrp];

    if (lane == 0) C[0] = 0.f;
    float carry = 0.f;
    int nchunk = (t + 32) >> 5;
    for (int c0 = 0; c0 < nchunk; c0++) {
        int j = c0 * 32 + lane;
        float s = (j <= t) ? Srow[j] : 0.f;
#pragma unroll
        for (int off = 1; off < 32; off <<= 1) {
            float y = __shfl_up_sync(0xffffffffu, s, off);
            if (lane >= off) s += y;
        }
        s += carry;
        C[1 + j] = s;
        carry = __shfl_sync(0xffffffffu, s, 31);
    }
    __syncwarp();

    float m = -1e30f;
    for (int e = lane; e <= t; e += 32) {
        float ce = C[1 + e];
        m = fmaxf(m, ce - C[e]);
        if (e >= 1) m = fmaxf(m, (ce - C[e - 1]) * 0.5f);
        if (e >= 2) m = fmaxf(m, (ce - C[e - 2]) * (1.f / 3.f));
    }
#pragma unroll
    for (int off = 16; off; off >>= 1) m = fmaxf(m, __shfl_xor_sync(0xffffffffu, m, off));

    for (int e = t + 1 + lane; e < bound + 2; e += 32) {
        T[e] = 0.f; U[e] = 0.f; V[e] = 0.f;
    }

    float sum = 0.f;
    for (int e = lane; e <= t; e += 32) {
        float ce = C[1 + e];
        float p1 = __expf(ce - C[e] - m);
        float p2 = (e >= 1) ? __expf((ce - C[e - 1]) * 0.5f - m) : 0.f;
        float p3 = (e >= 2) ? __expf((ce - C[e - 2]) * (1.f / 3.f) - m) : 0.f;
        T[e] = p1 + p2 + p3;
        U[e] = p2 + p3;
        V[e] = p3;
        sum += p1 + p2 + p3;
    }
#pragma unroll
    for (int off = 16; off; off >>= 1) sum += __shfl_xor_sync(0xffffffffu, sum, off);
    float inv = 1.f / sum;
    __syncwarp();

    for (int j = lane; j < bound; j += 32) {
        float g = (j <= t) ? (T[j] + U[j + 1] + V[j + 2]) * inv : 0.f;
        Grow[j] = __float2half(g);
    }
}

// ---------------------------------------------------------------------------
// av: attn = G @ Vt^T per bh, fp16 single-term. 128(M)x64(N), 4 warps, tri skip.
// ---------------------------------------------------------------------------
__global__ __launch_bounds__(128) void av_h()
{
    int tm = blockIdx.x, bh = blockIdx.y;
    const __half* A = g_Gh + (size_t)bh * 512 * 512;
    const __half* Bp = g_Vth + (size_t)bh * 64 * 512;
    __shared__ __half sA[2][128 * 40];
    __shared__ __half sB[2][64 * 40];
    const int tid = threadIdx.x, lane = tid & 31, wy = tid >> 5;
    const int row0 = tm * 128;
    const int rA = tid >> 2, cA = (tid & 3) * 8;

    uint32_t sAu = smem_u32(sA), sBu = smem_u32(sB);
    uint32_t aBase = sAu + (((wy * 32 + (lane & 15)) * 40 + ((lane >> 4) << 3)) << 1);
    uint32_t bBase = sBu + (((((lane >> 4) << 3) + (lane & 7)) * 40 + (lane & 8)) << 1);

    float acc[2][8][4];
#pragma unroll
    for (int i = 0; i < 2; i++)
#pragma unroll
        for (int j = 0; j < 8; j++)
#pragma unroll
            for (int q = 0; q < 4; q++) acc[i][j][q] = 0.f;

    uint4 pa[4], pb[2];
#define LDT_H(jc)                                                                   \
    {                                                                               \
        _Pragma("unroll") for (int i = 0; i < 4; i++)                               \
            pa[i] = *(const uint4*)(A + (size_t)(row0 + rA + i * 32) * 512 +        \
                                    (jc)*32 + cA);                                  \
        _Pragma("unroll") for (int i = 0; i < 2; i++)                               \
            pb[i] = *(const uint4*)(Bp + (size_t)(rA + i * 32) * 512 + (jc)*32 + cA); \
    }
#define STT_H(b)                                                                    \
    {                                                                               \
        _Pragma("unroll") for (int i = 0; i < 4; i++)                               \
            *(uint4*)&sA[b][(rA + i * 32) * 40 + cA] = pa[i];                       \
        _Pragma("unroll") for (int i = 0; i < 2; i++)                               \
            *(uint4*)&sB[b][(rA + i * 32) * 40 + cA] = pb[i];                       \
    }

    int nj = (tm + 1) * 4;
    LDT_H(0); STT_H(0); __syncthreads();
    for (int it = 0; it < nj; it++) {
        int b = it & 1;
        if (it < nj - 1) LDT_H(it + 1);
        uint32_t af[2][2][4], bfr[4][2][4];
        uint32_t aB = aBase + b * 10240, bB = bBase + b * 5120;
#pragma unroll
        for (int mi = 0; mi < 2; mi++)
#pragma unroll
            for (int ks = 0; ks < 2; ks++) ldsm4(af[mi][ks], aB + mi * 1280 + ks * 32);
#pragma unroll
        for (int ng = 0; ng < 4; ng++)
#pragma unroll
            for (int ks = 0; ks < 2; ks++) ldsm4(bfr[ng][ks], bB + ng * 1280 + ks * 32);
#pragma unroll
        for (int ks = 0; ks < 2; ks++)
#pragma unroll
            for (int mi = 0; mi < 2; mi++)
#pragma unroll
                for (int ni = 0; ni < 8; ni++)
                    mma_f16(acc[mi][ni], af[mi][ks],
                            bfr[ni >> 1][ks][(ni & 1) * 2],
                            bfr[ni >> 1][ks][(ni & 1) * 2 + 1]);
        if (it < nj - 1) { STT_H(b ^ 1); __syncthreads(); }
    }

    int b_ = bh >> 3, h_ = bh & 7;
#pragma unroll
    for (int mi = 0; mi < 2; mi++)
#pragma unroll
        for (int ni = 0; ni < 8; ni++) {
            int t0 = row0 + wy * 32 + mi * 16 + (lane >> 2);
            int d = ni * 8 + (lane & 3) * 2;
#pragma unroll
            for (int half = 0; half < 2; half++) {
                int t = t0 + half * 8;
                __half2 hv = __floats2half2_rn(acc[mi][ni][half * 2],
                                               acc[mi][ni][half * 2 + 1]);
                *(__half2*)(g_Aath + ((size_t)(b_ * 512 + t)) * 512 + h_ * 64 + d) = hv;
            }
        }
}

// ---------------------------------------------------------------------------
extern "C" void kernel_launch(void* const* d_in, const int* in_sizes, int n_in,
                              void* d_out, int out_size)
{
    const float* q  = (const float*)d_in[0];
    const float* k  = (const float*)d_in[1];
    const float* v  = (const float*)d_in[2];
    // d_in[3] = attn_mask — analytic (area end <= t), unused.
    const float* Wq = (const float*)d_in[4];
    const float* bq = (const float*)d_in[5];
    const float* Wk = (const float*)d_in[6];
    const float* bk = (const float*)d_in[7];
    const float* Wv = (const float*)d_in[8];
    const float* bv = (const float*)d_in[9];
    const float* Wo = (const float*)d_in[10];
    const float* bo = (const float*)d_in[11];
    float* out = (float*)d_out;

    cudaFuncSetAttribute(mma_gemm<0>, cudaFuncAttributeMaxDynamicSharedMemorySize, DSMEM);
    cudaFuncSetAttribute(mma_gemm<1>, cudaFuncAttributeMaxDynamicSharedMemorySize, DSMEM);
    cudaFuncSetAttribute(gemm_h<0>, cudaFuncAttributeMaxDynamicSharedMemorySize, DSMEM);
    cudaFuncSetAttribute(gemm_h<1>, cudaFuncAttributeMaxDynamicSharedMemorySize, DSMEM);
    cudaFuncSetAttribute(qk_mma, cudaFuncAttributeMaxDynamicSharedMemorySize, 81920);

    convW_all<<<dim3(16, 16, 2), 256>>>(Wq, Wk);
    convW_h<<<dim3(16, 16, 2), 256>>>(Wv, Wo);
    convX_all<<<dim3(4096, 1, 2), 256>>>(q, k);
    convV_h<<<4096, 256>>>(v);

    dim3 gG(2, 64);
    mma_gemm<0><<<gG, 256, DSMEM>>>(bq);
    mma_gemm<1><<<gG, 256, DSMEM>>>(bk);
    gemm_h<0><<<gG, 256, DSMEM>>>(bv, nullptr);

    vtrans<<<dim3(8, 128), 256>>>();
    qk_mma<<<dim3(4, 4, 128), 256, 81920>>>();
    area_softmax_kernel<<<dim3(128, 128), 128>>>();
    av_h<<<dim3(4, 128), 128>>>();

    gemm_h<1><<<gG, 256, DSMEM>>>(bo, out);
}

// round 13
// speedup vs baseline: 1.0113x; 1.0113x over previous
#include <cuda_runtime.h>
#include <cuda_bf16.h>
#include <cuda_fp16.h>
#include <cstdint>

// ---------------------------------------------------------------------------
// MultiHeadAreaAttention. Precision-tiered tensor-core pipeline:
//   Q/K chain (proj Q, proj K, QK^T): split-bf16 3-term (needs ~1e-4 logits)
//   V path (proj V, G@V, out proj):   single-term fp16 (tolerates ~1e-4 rel)
// Round 13: 3-stage cp.async pipeline in the dense GEMMs (2-stage exposed
// stage-load latency: tensor=45% with DRAM=4% in R7/R12 profiles).
// ---------------------------------------------------------------------------

#define BH_ 128
#define L_  512
typedef __nv_bfloat16 bf16;

// bf16 split operands for Q/K chain
__device__ bf16 g_Aq[(size_t)8192 * 1024];
__device__ bf16 g_Ak[(size_t)8192 * 1024];
__device__ bf16 g_Bq[512 * 1024];
__device__ bf16 g_Bk[512 * 1024];
__device__ bf16 g_Qs[(size_t)BH_ * 512 * 128];  // [bh][l][hi64|lo64]
__device__ bf16 g_Ks[(size_t)BH_ * 512 * 128];

// fp16 single operands for V path
__device__ __half g_Avh[(size_t)8192 * 512];     // fp16(v)
__device__ __half g_Bvh[512 * 512];              // fp16(Wv)^T  (n-major)
__device__ __half g_Boh[512 * 512];              // fp16(Wo)^T
__device__ __half g_Vth[(size_t)BH_ * 64 * 512]; // V^T per bh
__device__ __half g_Gh[(size_t)BH_ * 512 * 512]; // softmax-folded G
__device__ __half g_Aath[(size_t)8192 * 512];    // attn rows [b*512+t][h*64+d]

__device__ float g_Vh[(size_t)BH_ * 512 * 64];   // fp32 V heads (proj V out)
__device__ float g_S[(size_t)BH_ * 512 * 512];   // scores fp32

// ---------------------------------------------------------------------------
static __device__ __forceinline__ uint32_t smem_u32(const void* p) {
    uint32_t a;
    asm("{ .reg .u64 t; cvta.to.shared.u64 t, %1; cvt.u32.u64 %0, t; }"
        : "=r"(a) : "l"(p));
    return a;
}
static __device__ __forceinline__ void ldsm4(uint32_t* r, uint32_t a) {
    asm volatile("ldmatrix.sync.aligned.m8n8.x4.shared.b16 {%0,%1,%2,%3}, [%4];"
                 : "=r"(r[0]), "=r"(r[1]), "=r"(r[2]), "=r"(r[3]) : "r"(a));
}
static __device__ __forceinline__ void mma_bf16(float* d, const uint32_t* a,
                                                uint32_t b0, uint32_t b1) {
    asm volatile(
        "mma.sync.aligned.m16n8k16.row.col.f32.bf16.bf16.f32 "
        "{%0,%1,%2,%3},{%4,%5,%6,%7},{%8,%9},{%0,%1,%2,%3};"
        : "+f"(d[0]), "+f"(d[1]), "+f"(d[2]), "+f"(d[3])
        : "r"(a[0]), "r"(a[1]), "r"(a[2]), "r"(a[3]), "r"(b0), "r"(b1));
}
static __device__ __forceinline__ void mma_f16(float* d, const uint32_t* a,
                                               uint32_t b0, uint32_t b1) {
    asm volatile(
        "mma.sync.aligned.m16n8k16.row.col.f32.f16.f16.f32 "
        "{%0,%1,%2,%3},{%4,%5,%6,%7},{%8,%9},{%0,%1,%2,%3};"
        : "+f"(d[0]), "+f"(d[1]), "+f"(d[2]), "+f"(d[3])
        : "r"(a[0]), "r"(a[1]), "r"(a[2]), "r"(a[3]), "r"(b0), "r"(b1));
}
#define CP16(dst, src)                                                         \
    asm volatile("cp.async.cg.shared.global [%0], [%1], 16;" ::"r"(dst),       \
                 "l"(src))
#define CP_COMMIT() asm volatile("cp.async.commit_group;")
#define CP_WAIT(n) asm volatile("cp.async.wait_group %0;" ::"n"(n))

// ---------------------------------------------------------------------------
// conversions
// ---------------------------------------------------------------------------
__global__ __launch_bounds__(256) void convX_all(const float* __restrict__ q,
                                                 const float* __restrict__ k)
{
    int z = blockIdx.z;
    const float* X = (z == 0) ? q : k;
    bf16* A = (z == 0) ? g_Aq : g_Ak;
    size_t i4 = (size_t)blockIdx.x * 256 + threadIdx.x;
    size_t r = i4 >> 7;
    int kq = (int)(i4 & 127) * 4;
    float4 x = *(const float4*)(X + r * 512 + kq);
    bf16 h0 = __float2bfloat16(x.x), h1 = __float2bfloat16(x.y);
    bf16 h2 = __float2bfloat16(x.z), h3 = __float2bfloat16(x.w);
    bf16 l0 = __float2bfloat16(x.x - __bfloat162float(h0));
    bf16 l1 = __float2bfloat16(x.y - __bfloat162float(h1));
    bf16 l2 = __float2bfloat16(x.z - __bfloat162float(h2));
    bf16 l3 = __float2bfloat16(x.w - __bfloat162float(h3));
    __nv_bfloat162* p0 = (__nv_bfloat162*)(A + r * 1024 + kq);
    __nv_bfloat162* p1 = (__nv_bfloat162*)(A + r * 1024 + 512 + kq);
    p0[0] = __halves2bfloat162(h0, h1);
    p0[1] = __halves2bfloat162(h2, h3);
    p1[0] = __halves2bfloat162(l0, l1);
    p1[1] = __halves2bfloat162(l2, l3);
}

__global__ __launch_bounds__(256) void convV_h(const float* __restrict__ v)
{
    size_t idx = (size_t)blockIdx.x * 256 + threadIdx.x;
    float4 x = ((const float4*)v)[idx];
    __half2* p = (__half2*)(g_Avh + idx * 4);
    p[0] = __floats2half2_rn(x.x, x.y);
    p[1] = __floats2half2_rn(x.z, x.w);
}

// all four weights in one launch: z 0/1 -> bf16 split (Wq/Wk), 2/3 -> fp16 (Wv/Wo)
__global__ __launch_bounds__(256) void convW_all(const float* __restrict__ Wq,
                                                 const float* __restrict__ Wk,
                                                 const float* __restrict__ Wv,
                                                 const float* __restrict__ Wo)
{
    __shared__ float t[32][33];
    int z = blockIdx.z;
    const float* W = (z == 0) ? Wq : (z == 1) ? Wk : (z == 2) ? Wv : Wo;
    int n0 = blockIdx.x * 32, k0 = blockIdx.y * 32;
    int tx = threadIdx.x & 31, ty = threadIdx.x >> 5;
#pragma unroll
    for (int i = 0; i < 4; i++)
        t[ty + i * 8][tx] = W[(size_t)(k0 + ty + i * 8) * 512 + n0 + tx];
    __syncthreads();
    if (z < 2) {
        bf16* Bp = (z == 0) ? g_Bq : g_Bk;
#pragma unroll
        for (int i = 0; i < 4; i++) {
            int n = n0 + ty + i * 8, k = k0 + tx;
            float w = t[tx][ty + i * 8];
            bf16 h = __float2bfloat16(w);
            bf16 l = __float2bfloat16(w - __bfloat162float(h));
            Bp[(size_t)n * 1024 + k]       = h;
            Bp[(size_t)n * 1024 + 512 + k] = l;
        }
    } else {
        __half* Bp = (z == 2) ? g_Bvh : g_Boh;
#pragma unroll
        for (int i = 0; i < 4; i++) {
            int n = n0 + ty + i * 8, k = k0 + tx;
            Bp[(size_t)n * 512 + k] = __float2half(t[tx][ty + i * 8]);
        }
    }
}

// ---------------------------------------------------------------------------
// bf16 3-term dense GEMM (Q/K projections).
// 256 threads / 8 warps (2x4), block tile 128x256, warp tile 64x64, BK=32.
// Stage: A hi(10240) A lo(10240) B hi(20480) B lo(20480) = 61440; 3 stages.
// ---------------------------------------------------------------------------
#define PANEL 10240
#define BPANEL 20480
#define DSTAGE 61440
#define DSMEM3 184320

template <int MODE>  // 0: Q proj -> g_Qs ; 1: K proj -> g_Ks
__global__ __launch_bounds__(256) void mma_gemm(const float* __restrict__ bias)
{
    const bf16* A  = (MODE == 0) ? g_Aq : g_Ak;
    const bf16* Bp = (MODE == 0) ? g_Bq : g_Bk;
    extern __shared__ char sm[];
    uint32_t sb = smem_u32(sm);
    const int tid = threadIdx.x, lane = tid & 31, wid = tid >> 5;
    const int wy = wid >> 2, wx = wid & 3;
    const int row0 = blockIdx.y * 128, col0 = blockIdx.x * 256;

    const uint32_t aOff = ((wy * 64 + (lane & 15)) * 40 + ((lane >> 4) << 3)) * 2;
    const uint32_t bOff =
        ((wx * 64 + ((lane >> 4) << 3) + (lane & 7)) * 40 + (lane & 8)) * 2;

    float acc[4][8][4];
#pragma unroll
    for (int i = 0; i < 4; i++)
#pragma unroll
        for (int j = 0; j < 8; j++)
#pragma unroll
            for (int q = 0; q < 4; q++) acc[i][j][q] = 0.f;

#define FILL_D(kk, st)                                                          \
    {                                                                           \
        uint32_t stb = sb + (uint32_t)(st)*DSTAGE;                              \
        _Pragma("unroll") for (int i = 0; i < 2; i++)                           \
        {                                                                       \
            int s = tid + i * 256;                                              \
            int r = s >> 2, c = s & 3;                                          \
            uint32_t off = (uint32_t)(r * 40 + c * 8) * 2;                      \
            const bf16* a0 = A + (size_t)(row0 + r) * 1024 + (kk)*32 + c * 8;   \
            CP16(stb + off, a0);                                                \
            CP16(stb + PANEL + off, a0 + 512);                                  \
        }                                                                       \
        _Pragma("unroll") for (int i = 0; i < 4; i++)                           \
        {                                                                       \
            int s = tid + i * 256;                                              \
            int r = s >> 2, c = s & 3;                                          \
            uint32_t off = (uint32_t)(r * 40 + c * 8) * 2;                      \
            const bf16* b0 = Bp + (size_t)(col0 + r) * 1024 + (kk)*32 + c * 8;  \
            CP16(stb + 2 * PANEL + off, b0);                                    \
            CP16(stb + 2 * PANEL + BPANEL + off, b0 + 512);                     \
        }                                                                       \
        CP_COMMIT();                                                            \
    }

    FILL_D(0, 0);
    FILL_D(1, 1);
    FILL_D(2, 2);
    int st = 0;
    for (int kk = 0; kk < 16; kk++) {
        if (kk < 14) CP_WAIT(2);
        else if (kk == 14) CP_WAIT(1);
        else CP_WAIT(0);
        __syncthreads();
        uint32_t stb = sb + (uint32_t)st * DSTAGE;
#pragma unroll
        for (int ks = 0; ks < 2; ks++) {
            uint32_t ah[4][4], al[4][4], bh[4][4], bl[4][4];
#pragma unroll
            for (int mi = 0; mi < 4; mi++) {
                ldsm4(ah[mi], stb + aOff + mi * 1280 + ks * 32);
                ldsm4(al[mi], stb + PANEL + aOff + mi * 1280 + ks * 32);
            }
#pragma unroll
            for (int ng = 0; ng < 4; ng++) {
                ldsm4(bh[ng], stb + 2 * PANEL + bOff + ng * 1280 + ks * 32);
                ldsm4(bl[ng], stb + 2 * PANEL + BPANEL + bOff + ng * 1280 + ks * 32);
            }
#pragma unroll
            for (int mi = 0; mi < 4; mi++)
#pragma unroll
                for (int ni = 0; ni < 8; ni++) {
                    uint32_t bh0 = bh[ni >> 1][(ni & 1) * 2];
                    uint32_t bh1 = bh[ni >> 1][(ni & 1) * 2 + 1];
                    mma_bf16(acc[mi][ni], ah[mi], bh0, bh1);
                    mma_bf16(acc[mi][ni], al[mi], bh0, bh1);
                    mma_bf16(acc[mi][ni], ah[mi],
                             bl[ni >> 1][(ni & 1) * 2],
                             bl[ni >> 1][(ni & 1) * 2 + 1]);
                }
        }
        __syncthreads();
        if (kk + 3 < 16) FILL_D(kk + 3, st);
        st = (st == 2) ? 0 : st + 1;
    }

#pragma unroll
    for (int mi = 0; mi < 4; mi++)
#pragma unroll
        for (int ni = 0; ni < 8; ni++) {
            int r0 = row0 + wy * 64 + mi * 16 + (lane >> 2);
            int cc = col0 + wx * 64 + ni * 8 + (lane & 3) * 2;
            float b0 = __ldg(&bias[cc]), b1 = __ldg(&bias[cc + 1]);
#pragma unroll
            for (int half = 0; half < 2; half++) {
                int r = r0 + half * 8;
                float v0 = acc[mi][ni][half * 2] + b0;
                float v1 = acc[mi][ni][half * 2 + 1] + b1;
                int bh = ((r >> 9) << 3) + (cc >> 6), l = r & 511, d = cc & 63;
                bf16 h0 = __float2bfloat16(v0), h1 = __float2bfloat16(v1);
                bf16 l0 = __float2bfloat16(v0 - __bfloat162float(h0));
                bf16 l1 = __float2bfloat16(v1 - __bfloat162float(h1));
                bf16* dst =
                    ((MODE == 0) ? g_Qs : g_Ks) + ((size_t)bh * 512 + l) * 128 + d;
                *(__nv_bfloat162*)dst        = __halves2bfloat162(h0, h1);
                *(__nv_bfloat162*)(dst + 64) = __halves2bfloat162(l0, l1);
            }
        }
}

// ---------------------------------------------------------------------------
// fp16 single-term dense GEMM. 256 threads / 8 warps (2x4), tile 128x256.
// BK=64 as two k32 sub-panels; 3 stages.
// MODE 0: V proj -> g_Vh fp32 head-split (+bv); MODE 1: out -> Y (+bo)
// ---------------------------------------------------------------------------
template <int MODE>
__global__ __launch_bounds__(256) void gemm_h(const float* __restrict__ bias,
                                              float* __restrict__ Y)
{
    const __half* A = (MODE == 0) ? g_Avh : g_Aath;
    const __half* B = (MODE == 0) ? g_Bvh : g_Boh;
    extern __shared__ char sm[];
    uint32_t sb = smem_u32(sm);
    const int tid = threadIdx.x, lane = tid & 31, wid = tid >> 5;
    const int wy = wid >> 2, wx = wid & 3;
    const int row0 = blockIdx.y * 128, col0 = blockIdx.x * 256;

    const uint32_t aOff = ((wy * 64 + (lane & 15)) * 40 + ((lane >> 4) << 3)) * 2;
    const uint32_t bOff =
        ((wx * 64 + ((lane >> 4) << 3) + (lane & 7)) * 40 + (lane & 8)) * 2;

    float acc[4][8][4];
#pragma unroll
    for (int i = 0; i < 4; i++)
#pragma unroll
        for (int j = 0; j < 8; j++)
#pragma unroll
            for (int q = 0; q < 4; q++) acc[i][j][q] = 0.f;

#define FILL_H(kk, st)                                                          \
    {                                                                           \
        uint32_t stb = sb + (uint32_t)(st)*DSTAGE;                              \
        _Pragma("unroll") for (int i = 0; i < 2; i++)                           \
        {                                                                       \
            int s = tid + i * 256;                                              \
            int r = s >> 2, c = s & 3;                                          \
            uint32_t off = (uint32_t)(r * 40 + c * 8) * 2;                      \
            const __half* a0 = A + (size_t)(row0 + r) * 512 + (kk)*64 + c * 8;  \
            CP16(stb + off, a0);                                                \
            CP16(stb + PANEL + off, a0 + 32);                                   \
        }                                                                       \
        _Pragma("unroll") for (int i = 0; i < 4; i++)                           \
        {                                                                       \
            int s = tid + i * 256;                                              \
            int r = s >> 2, c = s & 3;                                          \
            uint32_t off = (uint32_t)(r * 40 + c * 8) * 2;                      \
            const __half* b0 = B + (size_t)(col0 + r) * 512 + (kk)*64 + c * 8;  \
            CP16(stb + 2 * PANEL + off, b0);                                    \
            CP16(stb + 2 * PANEL + BPANEL + off, b0 + 32);                      \
        }                                                                       \
        CP_COMMIT();                                                            \
    }

    FILL_H(0, 0);
    FILL_H(1, 1);
    FILL_H(2, 2);
    int st = 0;
    for (int kk = 0; kk < 8; kk++) {
        if (kk < 6) CP_WAIT(2);
        else if (kk == 6) CP_WAIT(1);
        else CP_WAIT(0);
        __syncthreads();
        uint32_t stb = sb + (uint32_t)st * DSTAGE;
#pragma unroll
        for (int sub = 0; sub < 2; sub++) {
            uint32_t ap = stb + sub * PANEL;
            uint32_t bp = stb + 2 * PANEL + sub * BPANEL;
#pragma unroll
            for (int ks = 0; ks < 2; ks++) {
                uint32_t af[4][4], bfr[4][4];
#pragma unroll
                for (int mi = 0; mi < 4; mi++)
                    ldsm4(af[mi], ap + aOff + mi * 1280 + ks * 32);
#pragma unroll
                for (int ng = 0; ng < 4; ng++)
                    ldsm4(bfr[ng], bp + bOff + ng * 1280 + ks * 32);
#pragma unroll
                for (int mi = 0; mi < 4; mi++)
#pragma unroll
                    for (int ni = 0; ni < 8; ni++)
                        mma_f16(acc[mi][ni], af[mi],
                                bfr[ni >> 1][(ni & 1) * 2],
                                bfr[ni >> 1][(ni & 1) * 2 + 1]);
            }
        }
        __syncthreads();
        if (kk + 3 < 8) FILL_H(kk + 3, st);
        st = (st == 2) ? 0 : st + 1;
    }

#pragma unroll
    for (int mi = 0; mi < 4; mi++)
#pragma unroll
        for (int ni = 0; ni < 8; ni++) {
            int r0 = row0 + wy * 64 + mi * 16 + (lane >> 2);
            int cc = col0 + wx * 64 + ni * 8 + (lane & 3) * 2;
            float b0 = __ldg(&bias[cc]), b1 = __ldg(&bias[cc + 1]);
#pragma unroll
            for (int half = 0; half < 2; half++) {
                int r = r0 + half * 8;
                float v0 = acc[mi][ni][half * 2] + b0;
                float v1 = acc[mi][ni][half * 2 + 1] + b1;
                if (MODE == 1) {
                    *(float2*)(Y + (size_t)r * 512 + cc) = make_float2(v0, v1);
                } else {
                    int bh = ((r >> 9) << 3) + (cc >> 6), l = r & 511, d = cc & 63;
                    *(float2*)(g_Vh + ((size_t)bh * 512 + l) * 64 + d) =
                        make_float2(v0, v1);
                }
            }
        }
}

// ---------------------------------------------------------------------------
// V transpose: g_Vh [bh][512][64] fp32 -> g_Vth [bh][64][512] fp16
// ---------------------------------------------------------------------------
__global__ __launch_bounds__(256) void vtrans()
{
    int l0 = blockIdx.x * 64, bh = blockIdx.y;
    __shared__ float sm[64][68];
    const float* V = g_Vh + (size_t)bh * 512 * 64;
    int tid = threadIdx.x;
#pragma unroll
    for (int i = 0; i < 4; i++) {
        int idx4 = tid + i * 256;
        int r = idx4 >> 4, c4 = (idx4 & 15) * 4;
        *(float4*)&sm[r][c4] = *(const float4*)(V + (size_t)(l0 + r) * 64 + c4);
    }
    __syncthreads();
    __half* O = g_Vth + (size_t)bh * 64 * 512;
#pragma unroll
    for (int i = 0; i < 16; i++) {
        int e = tid + i * 256;
        int d = e >> 6, l = e & 63;
        O[(size_t)d * 512 + l0 + l] = __float2half(sm[l][d]);
    }
}

// ---------------------------------------------------------------------------
// qk: S = Qs @ Ks^T per bh (bf16 3-term). 256 threads / 8 warps (2 my x 4 nx),
// warp tile 64x32, whole split-K resident (8 panels x 10240 = 81920).
// ---------------------------------------------------------------------------
__global__ __launch_bounds__(256) void qk_mma()
{
    int tk = blockIdx.x, tq = blockIdx.y, bh = blockIdx.z;
    if (tk > tq) return;
    const bf16* Aq = g_Qs + (size_t)bh * 512 * 128;
    const bf16* Bk = g_Ks + (size_t)bh * 512 * 128;
    extern __shared__ char sm[];
    uint32_t sb = smem_u32(sm);
    const int tid = threadIdx.x, lane = tid & 31, wid = tid >> 5;
    const int wy = wid >> 2, wx = wid & 3;
    const int row0 = tq * 128, col0 = tk * 128;

    const uint32_t aOff = ((wy * 64 + (lane & 15)) * 40 + ((lane >> 4) << 3)) * 2;
    const uint32_t bOff =
        ((wx * 32 + ((lane >> 4) << 3) + (lane & 7)) * 40 + (lane & 8)) * 2;

#pragma unroll
    for (int p = 0; p < 4; p++) {  // p = part*2 + kchunk
        int part = p >> 1, kk = p & 1;
        int colb = part * 64 + kk * 32;
#pragma unroll
        for (int i = 0; i < 2; i++) {
            int s = tid + i * 256;
            int r = s >> 2, c = s & 3;
            uint32_t off = (uint32_t)(r * 40 + c * 8) * 2;
            CP16(sb + p * PANEL + off,
                 Aq + (size_t)(row0 + r) * 128 + colb + c * 8);
            CP16(sb + (4 + p) * PANEL + off,
                 Bk + (size_t)(col0 + r) * 128 + colb + c * 8);
        }
    }
    CP_COMMIT();

    float acc[4][4][4];
#pragma unroll
    for (int i = 0; i < 4; i++)
#pragma unroll
        for (int j = 0; j < 4; j++)
#pragma unroll
            for (int q = 0; q < 4; q++) acc[i][j][q] = 0.f;

    CP_WAIT(0);
    __syncthreads();

#pragma unroll
    for (int kk = 0; kk < 2; kk++) {
        uint32_t qh = sb + kk * PANEL, ql = sb + (2 + kk) * PANEL;
        uint32_t kh = sb + (4 + kk) * PANEL, kl = sb + (6 + kk) * PANEL;
#pragma unroll
        for (int ks = 0; ks < 2; ks++) {
            uint32_t ah[4][4], al[4][4], bh[2][4], bl[2][4];
#pragma unroll
            for (int mi = 0; mi < 4; mi++) {
                ldsm4(ah[mi], qh + aOff + mi * 1280 + ks * 32);
                ldsm4(al[mi], ql + aOff + mi * 1280 + ks * 32);
            }
#pragma unroll
            for (int ng = 0; ng < 2; ng++) {
                ldsm4(bh[ng], kh + bOff + ng * 1280 + ks * 32);
                ldsm4(bl[ng], kl + bOff + ng * 1280 + ks * 32);
            }
#pragma unroll
            for (int mi = 0; mi < 4; mi++)
#pragma unroll
                for (int ni = 0; ni < 4; ni++) {
                    uint32_t bh0 = bh[ni >> 1][(ni & 1) * 2];
                    uint32_t bh1 = bh[ni >> 1][(ni & 1) * 2 + 1];
                    mma_bf16(acc[mi][ni], ah[mi], bh0, bh1);
                    mma_bf16(acc[mi][ni], al[mi], bh0, bh1);
                    mma_bf16(acc[mi][ni], ah[mi],
                             bl[ni >> 1][(ni & 1) * 2],
                             bl[ni >> 1][(ni & 1) * 2 + 1]);
                }
        }
    }

    float* Smat = g_S + (size_t)bh * 512 * 512;
#pragma unroll
    for (int mi = 0; mi < 4; mi++)
#pragma unroll
        for (int ni = 0; ni < 4; ni++) {
            int r = row0 + wy * 64 + mi * 16 + (lane >> 2);
            int cc = col0 + wx * 32 + ni * 8 + (lane & 3) * 2;
            *(float2*)(Smat + (size_t)r * 512 + cc) =
                make_float2(acc[mi][ni][0], acc[mi][ni][1]);
            *(float2*)(Smat + (size_t)(r + 8) * 512 + cc) =
                make_float2(acc[mi][ni][2], acc[mi][ni][3]);
        }
}

// ---------------------------------------------------------------------------
// Per-row cumsum + area softmax + fold; emits G fp16 up to tile bound.
// ---------------------------------------------------------------------------
__global__ __launch_bounds__(128) void area_softmax_kernel()
{
    __shared__ float Cb[4][516];
    __shared__ float Tb[4][516];
    __shared__ float Ub[4][516];
    __shared__ float Vb[4][516];

    int wrp = threadIdx.x >> 5;
    int lane = threadIdx.x & 31;
    int t = blockIdx.x * 4 + wrp;
    int bh = blockIdx.y;
    int bound = ((t >> 7) + 1) << 7;  // av reads j < bound only

    const float* Srow = g_S + ((size_t)bh * L_ + t) * L_;
    __half* Grow = g_Gh + ((size_t)bh * L_ + t) * 512;
    float* C = Cb[wrp];
    float* T = Tb[wrp];
    float* U = Ub[wrp];
    float* V = Vb[wrp];

    if (lane == 0) C[0] = 0.f;
    float carry = 0.f;
    int nchunk = (t + 32) >> 5;
    for (int c0 = 0; c0 < nchunk; c0++) {
        int j = c0 * 32 + lane;
        float s = (j <= t) ? Srow[j] : 0.f;
#pragma unroll
        for (int off = 1; off < 32; off <<= 1) {
            float y = __shfl_up_sync(0xffffffffu, s, off);
            if (lane >= off) s += y;
        }
        s += carry;
        C[1 + j] = s;
        carry = __shfl_sync(0xffffffffu, s, 31);
    }
    __syncwarp();

    float m = -1e30f;
    for (int e = lane; e <= t; e += 32) {
        float ce = C[1 + e];
        m = fmaxf(m, ce - C[e]);
        if (e >= 1) m = fmaxf(m, (ce - C[e - 1]) * 0.5f);
        if (e >= 2) m = fmaxf(m, (ce - C[e - 2]) * (1.f / 3.f));
    }
#pragma unroll
    for (int off = 16; off; off >>= 1) m = fmaxf(m, __shfl_xor_sync(0xffffffffu, m, off));

    for (int e = t + 1 + lane; e < bound + 2; e += 32) {
        T[e] = 0.f; U[e] = 0.f; V[e] = 0.f;
    }

    float sum = 0.f;
    for (int e = lane; e <= t; e += 32) {
        float ce = C[1 + e];
        float p1 = __expf(ce - C[e] - m);
        float p2 = (e >= 1) ? __expf((ce - C[e - 1]) * 0.5f - m) : 0.f;
        float p3 = (e >= 2) ? __expf((ce - C[e - 2]) * (1.f / 3.f) - m) : 0.f;
        T[e] = p1 + p2 + p3;
        U[e] = p2 + p3;
        V[e] = p3;
        sum += p1 + p2 + p3;
    }
#pragma unroll
    for (int off = 16; off; off >>= 1) sum += __shfl_xor_sync(0xffffffffu, sum, off);
    float inv = 1.f / sum;
    __syncwarp();

    for (int j = lane; j < bound; j += 32) {
        float g = (j <= t) ? (T[j] + U[j + 1] + V[j + 2]) * inv : 0.f;
        Grow[j] = __float2half(g);
    }
}

// ---------------------------------------------------------------------------
// av: attn = G @ Vt^T per bh, fp16 single-term. 128(M)x64(N), 4 warps, tri skip.
// ---------------------------------------------------------------------------
__global__ __launch_bounds__(128) void av_h()
{
    int tm = blockIdx.x, bh = blockIdx.y;
    const __half* A = g_Gh + (size_t)bh * 512 * 512;
    const __half* Bp = g_Vth + (size_t)bh * 64 * 512;
    __shared__ __half sA[2][128 * 40];
    __shared__ __half sB[2][64 * 40];
    const int tid = threadIdx.x, lane = tid & 31, wy = tid >> 5;
    const int row0 = tm * 128;
    const int rA = tid >> 2, cA = (tid & 3) * 8;

    uint32_t sAu = smem_u32(sA), sBu = smem_u32(sB);
    uint32_t aBase = sAu + (((wy * 32 + (lane & 15)) * 40 + ((lane >> 4) << 3)) << 1);
    uint32_t bBase = sBu + (((((lane >> 4) << 3) + (lane & 7)) * 40 + (lane & 8)) << 1);

    float acc[2][8][4];
#pragma unroll
    for (int i = 0; i < 2; i++)
#pragma unroll
        for (int j = 0; j < 8; j++)
#pragma unroll
            for (int q = 0; q < 4; q++) acc[i][j][q] = 0.f;

    uint4 pa[4], pb[2];
#define LDT_H(jc)                                                                   \
    {                                                                               \
        _Pragma("unroll") for (int i = 0; i < 4; i++)                               \
            pa[i] = *(const uint4*)(A + (size_t)(row0 + rA + i * 32) * 512 +        \
                                    (jc)*32 + cA);                                  \
        _Pragma("unroll") for (int i = 0; i < 2; i++)                               \
            pb[i] = *(const uint4*)(Bp + (size_t)(rA + i * 32) * 512 + (jc)*32 + cA); \
    }
#define STT_H(b)                                                                    \
    {                                                                               \
        _Pragma("unroll") for (int i = 0; i < 4; i++)                               \
            *(uint4*)&sA[b][(rA + i * 32) * 40 + cA] = pa[i];                       \
        _Pragma("unroll") for (int i = 0; i < 2; i++)                               \
            *(uint4*)&sB[b][(rA + i * 32) * 40 + cA] = pb[i];                       \
    }

    int nj = (tm + 1) * 4;
    LDT_H(0); STT_H(0); __syncthreads();
    for (int it = 0; it < nj; it++) {
        int b = it & 1;
        if (it < nj - 1) LDT_H(it + 1);
        uint32_t af[2][2][4], bfr[4][2][4];
        uint32_t aB = aBase + b * 10240, bB = bBase + b * 5120;
#pragma unroll
        for (int mi = 0; mi < 2; mi++)
#pragma unroll
            for (int ks = 0; ks < 2; ks++) ldsm4(af[mi][ks], aB + mi * 1280 + ks * 32);
#pragma unroll
        for (int ng = 0; ng < 4; ng++)
#pragma unroll
            for (int ks = 0; ks < 2; ks++) ldsm4(bfr[ng][ks], bB + ng * 1280 + ks * 32);
#pragma unroll
        for (int ks = 0; ks < 2; ks++)
#pragma unroll
            for (int mi = 0; mi < 2; mi++)
#pragma unroll
                for (int ni = 0; ni < 8; ni++)
                    mma_f16(acc[mi][ni], af[mi][ks],
                            bfr[ni >> 1][ks][(ni & 1) * 2],
                            bfr[ni >> 1][ks][(ni & 1) * 2 + 1]);
        if (it < nj - 1) { STT_H(b ^ 1); __syncthreads(); }
    }

    int b_ = bh >> 3, h_ = bh & 7;
#pragma unroll
    for (int mi = 0; mi < 2; mi++)
#pragma unroll
        for (int ni = 0; ni < 8; ni++) {
            int t0 = row0 + wy * 32 + mi * 16 + (lane >> 2);
            int d = ni * 8 + (lane & 3) * 2;
#pragma unroll
            for (int half = 0; half < 2; half++) {
                int t = t0 + half * 8;
                __half2 hv = __floats2half2_rn(acc[mi][ni][half * 2],
                                               acc[mi][ni][half * 2 + 1]);
                *(__half2*)(g_Aath + ((size_t)(b_ * 512 + t)) * 512 + h_ * 64 + d) = hv;
            }
        }
}

// ---------------------------------------------------------------------------
extern "C" void kernel_launch(void* const* d_in, const int* in_sizes, int n_in,
                              void* d_out, int out_size)
{
    const float* q  = (const float*)d_in[0];
    const float* k  = (const float*)d_in[1];
    const float* v  = (const float*)d_in[2];
    // d_in[3] = attn_mask — analytic (area end <= t), unused.
    const float* Wq = (const float*)d_in[4];
    const float* bq = (const float*)d_in[5];
    const float* Wk = (const float*)d_in[6];
    const float* bk = (const float*)d_in[7];
    const float* Wv = (const float*)d_in[8];
    const float* bv = (const float*)d_in[9];
    const float* Wo = (const float*)d_in[10];
    const float* bo = (const float*)d_in[11];
    float* out = (float*)d_out;

    cudaFuncSetAttribute(mma_gemm<0>, cudaFuncAttributeMaxDynamicSharedMemorySize, DSMEM3);
    cudaFuncSetAttribute(mma_gemm<1>, cudaFuncAttributeMaxDynamicSharedMemorySize, DSMEM3);
    cudaFuncSetAttribute(gemm_h<0>, cudaFuncAttributeMaxDynamicSharedMemorySize, DSMEM3);
    cudaFuncSetAttribute(gemm_h<1>, cudaFuncAttributeMaxDynamicSharedMemorySize, DSMEM3);
    cudaFuncSetAttribute(qk_mma, cudaFuncAttributeMaxDynamicSharedMemorySize, 81920);

    convW_all<<<dim3(16, 16, 4), 256>>>(Wq, Wk, Wv, Wo);
    convX_all<<<dim3(4096, 1, 2), 256>>>(q, k);
    convV_h<<<4096, 256>>>(v);

    dim3 gG(2, 64);
    mma_gemm<0><<<gG, 256, DSMEM3>>>(bq);
    mma_gemm<1><<<gG, 256, DSMEM3>>>(bk);
    gemm_h<0><<<gG, 256, DSMEM3>>>(bv, nullptr);

    vtrans<<<dim3(8, 128), 256>>>();
    qk_mma<<<dim3(4, 4, 128), 256, 81920>>>();
    area_softmax_kernel<<<dim3(128, 128), 128>>>();
    av_h<<<dim3(4, 128), 128>>>();

    gemm_h<1><<<gG, 256, DSMEM3>>>(bo, out);
}

// round 14
// speedup vs baseline: 1.0169x; 1.0055x over previous
#include <cuda_runtime.h>
#include <cuda_bf16.h>
#include <cuda_fp16.h>
#include <cstdint>

// ---------------------------------------------------------------------------
// MultiHeadAreaAttention. Precision-tiered tensor-core pipeline:
//   Q/K chain (proj Q, proj K, QK^T): split-bf16 3-term (needs ~1e-4 logits)
//   V path (proj V, G@V, out proj):   single-term fp16 (tolerates ~1e-4 rel)
// Round 14: 16 warps/SM occupancy experiment — 2 CTAs x 8 warps via
// __launch_bounds__(256,2), warp tile 32x64, ng-loop B fragments.
// ---------------------------------------------------------------------------

#define BH_ 128
#define L_  512
typedef __nv_bfloat16 bf16;

// bf16 split operands for Q/K chain
__device__ bf16 g_Aq[(size_t)8192 * 1024];
__device__ bf16 g_Ak[(size_t)8192 * 1024];
__device__ bf16 g_Bq[512 * 1024];
__device__ bf16 g_Bk[512 * 1024];
__device__ bf16 g_Qs[(size_t)BH_ * 512 * 128];  // [bh][l][hi64|lo64]
__device__ bf16 g_Ks[(size_t)BH_ * 512 * 128];

// fp16 single operands for V path
__device__ __half g_Avh[(size_t)8192 * 512];     // fp16(v)
__device__ __half g_Bvh[512 * 512];              // fp16(Wv)^T  (n-major)
__device__ __half g_Boh[512 * 512];              // fp16(Wo)^T
__device__ __half g_Vth[(size_t)BH_ * 64 * 512]; // V^T per bh
__device__ __half g_Gh[(size_t)BH_ * 512 * 512]; // softmax-folded G
__device__ __half g_Aath[(size_t)8192 * 512];    // attn rows [b*512+t][h*64+d]

__device__ float g_Vh[(size_t)BH_ * 512 * 64];   // fp32 V heads (proj V out)
__device__ float g_S[(size_t)BH_ * 512 * 512];   // scores fp32

// ---------------------------------------------------------------------------
static __device__ __forceinline__ uint32_t smem_u32(const void* p) {
    uint32_t a;
    asm("{ .reg .u64 t; cvta.to.shared.u64 t, %1; cvt.u32.u64 %0, t; }"
        : "=r"(a) : "l"(p));
    return a;
}
static __device__ __forceinline__ void ldsm4(uint32_t* r, uint32_t a) {
    asm volatile("ldmatrix.sync.aligned.m8n8.x4.shared.b16 {%0,%1,%2,%3}, [%4];"
                 : "=r"(r[0]), "=r"(r[1]), "=r"(r[2]), "=r"(r[3]) : "r"(a));
}
static __device__ __forceinline__ void mma_bf16(float* d, const uint32_t* a,
                                                uint32_t b0, uint32_t b1) {
    asm volatile(
        "mma.sync.aligned.m16n8k16.row.col.f32.bf16.bf16.f32 "
        "{%0,%1,%2,%3},{%4,%5,%6,%7},{%8,%9},{%0,%1,%2,%3};"
        : "+f"(d[0]), "+f"(d[1]), "+f"(d[2]), "+f"(d[3])
        : "r"(a[0]), "r"(a[1]), "r"(a[2]), "r"(a[3]), "r"(b0), "r"(b1));
}
static __device__ __forceinline__ void mma_f16(float* d, const uint32_t* a,
                                               uint32_t b0, uint32_t b1) {
    asm volatile(
        "mma.sync.aligned.m16n8k16.row.col.f32.f16.f16.f32 "
        "{%0,%1,%2,%3},{%4,%5,%6,%7},{%8,%9},{%0,%1,%2,%3};"
        : "+f"(d[0]), "+f"(d[1]), "+f"(d[2]), "+f"(d[3])
        : "r"(a[0]), "r"(a[1]), "r"(a[2]), "r"(a[3]), "r"(b0), "r"(b1));
}
#define CP16(dst, src)                                                         \
    asm volatile("cp.async.cg.shared.global [%0], [%1], 16;" ::"r"(dst),       \
                 "l"(src))
#define CP_COMMIT() asm volatile("cp.async.commit_group;")
#define CP_WAIT(n) asm volatile("cp.async.wait_group %0;" ::"n"(n))

// ---------------------------------------------------------------------------
// conversions (unchanged from R13)
// ---------------------------------------------------------------------------
__global__ __launch_bounds__(256) void convX_all(const float* __restrict__ q,
                                                 const float* __restrict__ k)
{
    int z = blockIdx.z;
    const float* X = (z == 0) ? q : k;
    bf16* A = (z == 0) ? g_Aq : g_Ak;
    size_t i4 = (size_t)blockIdx.x * 256 + threadIdx.x;
    size_t r = i4 >> 7;
    int kq = (int)(i4 & 127) * 4;
    float4 x = *(const float4*)(X + r * 512 + kq);
    bf16 h0 = __float2bfloat16(x.x), h1 = __float2bfloat16(x.y);
    bf16 h2 = __float2bfloat16(x.z), h3 = __float2bfloat16(x.w);
    bf16 l0 = __float2bfloat16(x.x - __bfloat162float(h0));
    bf16 l1 = __float2bfloat16(x.y - __bfloat162float(h1));
    bf16 l2 = __float2bfloat16(x.z - __bfloat162float(h2));
    bf16 l3 = __float2bfloat16(x.w - __bfloat162float(h3));
    __nv_bfloat162* p0 = (__nv_bfloat162*)(A + r * 1024 + kq);
    __nv_bfloat162* p1 = (__nv_bfloat162*)(A + r * 1024 + 512 + kq);
    p0[0] = __halves2bfloat162(h0, h1);
    p0[1] = __halves2bfloat162(h2, h3);
    p1[0] = __halves2bfloat162(l0, l1);
    p1[1] = __halves2bfloat162(l2, l3);
}

__global__ __launch_bounds__(256) void convV_h(const float* __restrict__ v)
{
    size_t idx = (size_t)blockIdx.x * 256 + threadIdx.x;
    float4 x = ((const float4*)v)[idx];
    __half2* p = (__half2*)(g_Avh + idx * 4);
    p[0] = __floats2half2_rn(x.x, x.y);
    p[1] = __floats2half2_rn(x.z, x.w);
}

__global__ __launch_bounds__(256) void convW_all(const float* __restrict__ Wq,
                                                 const float* __restrict__ Wk,
                                                 const float* __restrict__ Wv,
                                                 const float* __restrict__ Wo)
{
    __shared__ float t[32][33];
    int z = blockIdx.z;
    const float* W = (z == 0) ? Wq : (z == 1) ? Wk : (z == 2) ? Wv : Wo;
    int n0 = blockIdx.x * 32, k0 = blockIdx.y * 32;
    int tx = threadIdx.x & 31, ty = threadIdx.x >> 5;
#pragma unroll
    for (int i = 0; i < 4; i++)
        t[ty + i * 8][tx] = W[(size_t)(k0 + ty + i * 8) * 512 + n0 + tx];
    __syncthreads();
    if (z < 2) {
        bf16* Bp = (z == 0) ? g_Bq : g_Bk;
#pragma unroll
        for (int i = 0; i < 4; i++) {
            int n = n0 + ty + i * 8, k = k0 + tx;
            float w = t[tx][ty + i * 8];
            bf16 h = __float2bfloat16(w);
            bf16 l = __float2bfloat16(w - __bfloat162float(h));
            Bp[(size_t)n * 1024 + k]       = h;
            Bp[(size_t)n * 1024 + 512 + k] = l;
        }
    } else {
        __half* Bp = (z == 2) ? g_Bvh : g_Boh;
#pragma unroll
        for (int i = 0; i < 4; i++) {
            int n = n0 + ty + i * 8, k = k0 + tx;
            Bp[(size_t)n * 512 + k] = __float2half(t[tx][ty + i * 8]);
        }
    }
}

// ---------------------------------------------------------------------------
// bf16 3-term dense GEMM (Q/K projections). 16-warps/SM variant:
// 256 threads / 8 warps (4 wy x 2 wx), block 128x128, warp tile 32x64, BK=32.
// Stage: A hi + A lo + B hi + B lo, each 10240 = 40960; 2 stages = 81920.
// __launch_bounds__(256,2) -> 2 CTAs/SM (regs <= 128, smem 2x81920 = 160 KB).
// ---------------------------------------------------------------------------
#define PANEL 10240
#define QSTAGE 40960
#define QSMEM 81920

template <int MODE>  // 0: Q proj -> g_Qs ; 1: K proj -> g_Ks
__global__ __launch_bounds__(256, 2) void mma_gemm(const float* __restrict__ bias)
{
    const bf16* A  = (MODE == 0) ? g_Aq : g_Ak;
    const bf16* Bp = (MODE == 0) ? g_Bq : g_Bk;
    extern __shared__ char sm[];
    uint32_t sb = smem_u32(sm);
    const int tid = threadIdx.x, lane = tid & 31, wid = tid >> 5;
    const int wy = wid >> 1, wx = wid & 1;
    const int row0 = blockIdx.y * 128, col0 = blockIdx.x * 128;

    const uint32_t aOff = ((wy * 32 + (lane & 15)) * 40 + ((lane >> 4) << 3)) * 2;
    const uint32_t bOff =
        ((wx * 64 + ((lane >> 4) << 3) + (lane & 7)) * 40 + (lane & 8)) * 2;

    float acc[2][8][4];
#pragma unroll
    for (int i = 0; i < 2; i++)
#pragma unroll
        for (int j = 0; j < 8; j++)
#pragma unroll
            for (int q = 0; q < 4; q++) acc[i][j][q] = 0.f;

#define FILL_D(kk, st)                                                          \
    {                                                                           \
        uint32_t stb = sb + (uint32_t)(st)*QSTAGE;                              \
        _Pragma("unroll") for (int i = 0; i < 2; i++)                           \
        {                                                                       \
            int s = tid + i * 256;                                              \
            int r = s >> 2, c = s & 3;                                          \
            uint32_t off = (uint32_t)(r * 40 + c * 8) * 2;                      \
            const bf16* a0 = A + (size_t)(row0 + r) * 1024 + (kk)*32 + c * 8;   \
            const bf16* b0 = Bp + (size_t)(col0 + r) * 1024 + (kk)*32 + c * 8;  \
            CP16(stb + off, a0);                                                \
            CP16(stb + PANEL + off, a0 + 512);                                  \
            CP16(stb + 2 * PANEL + off, b0);                                    \
            CP16(stb + 3 * PANEL + off, b0 + 512);                              \
        }                                                                       \
        CP_COMMIT();                                                            \
    }

    FILL_D(0, 0);
    FILL_D(1, 1);
    for (int kk = 0; kk < 16; kk++) {
        if (kk < 15) CP_WAIT(1); else CP_WAIT(0);
        __syncthreads();
        uint32_t stb = sb + (uint32_t)(kk & 1) * QSTAGE;
#pragma unroll
        for (int ks = 0; ks < 2; ks++) {
            uint32_t ah[2][4], al[2][4];
#pragma unroll
            for (int mi = 0; mi < 2; mi++) {
                ldsm4(ah[mi], stb + aOff + mi * 1280 + ks * 32);
                ldsm4(al[mi], stb + PANEL + aOff + mi * 1280 + ks * 32);
            }
#pragma unroll
            for (int ng = 0; ng < 4; ng++) {
                uint32_t bh[4], bl[4];
                ldsm4(bh, stb + 2 * PANEL + bOff + ng * 1280 + ks * 32);
                ldsm4(bl, stb + 3 * PANEL + bOff + ng * 1280 + ks * 32);
#pragma unroll
                for (int mi = 0; mi < 2; mi++)
#pragma unroll
                    for (int p = 0; p < 2; p++) {
                        float* d = acc[mi][ng * 2 + p];
                        mma_bf16(d, ah[mi], bh[p * 2], bh[p * 2 + 1]);
                        mma_bf16(d, al[mi], bh[p * 2], bh[p * 2 + 1]);
                        mma_bf16(d, ah[mi], bl[p * 2], bl[p * 2 + 1]);
                    }
            }
        }
        __syncthreads();
        if (kk + 2 < 16) FILL_D(kk + 2, kk & 1);
    }

#pragma unroll
    for (int mi = 0; mi < 2; mi++)
#pragma unroll
        for (int ni = 0; ni < 8; ni++) {
            int r0 = row0 + wy * 32 + mi * 16 + (lane >> 2);
            int cc = col0 + wx * 64 + ni * 8 + (lane & 3) * 2;
            float b0 = __ldg(&bias[cc]), b1 = __ldg(&bias[cc + 1]);
#pragma unroll
            for (int half = 0; half < 2; half++) {
                int r = r0 + half * 8;
                float v0 = acc[mi][ni][half * 2] + b0;
                float v1 = acc[mi][ni][half * 2 + 1] + b1;
                int bh = ((r >> 9) << 3) + (cc >> 6), l = r & 511, d = cc & 63;
                bf16 h0 = __float2bfloat16(v0), h1 = __float2bfloat16(v1);
                bf16 l0 = __float2bfloat16(v0 - __bfloat162float(h0));
                bf16 l1 = __float2bfloat16(v1 - __bfloat162float(h1));
                bf16* dst =
                    ((MODE == 0) ? g_Qs : g_Ks) + ((size_t)bh * 512 + l) * 128 + d;
                *(__nv_bfloat162*)dst        = __halves2bfloat162(h0, h1);
                *(__nv_bfloat162*)(dst + 64) = __halves2bfloat162(l0, l1);
            }
        }
}

// ---------------------------------------------------------------------------
// fp16 single-term dense GEMM, 16-warps/SM variant. Block 128x128, 8 warps
// (4x2), warp tile 32x64. BK=64 as 2 k32 sub-panels; 2 stages = 81920.
// MODE 0: V proj -> g_Vh fp32 head-split (+bv); MODE 1: out -> Y (+bo)
// ---------------------------------------------------------------------------
template <int MODE>
__global__ __launch_bounds__(256, 2) void gemm_h(const float* __restrict__ bias,
                                                 float* __restrict__ Y)
{
    const __half* A = (MODE == 0) ? g_Avh : g_Aath;
    const __half* B = (MODE == 0) ? g_Bvh : g_Boh;
    extern __shared__ char sm[];
    uint32_t sb = smem_u32(sm);
    const int tid = threadIdx.x, lane = tid & 31, wid = tid >> 5;
    const int wy = wid >> 1, wx = wid & 1;
    const int row0 = blockIdx.y * 128, col0 = blockIdx.x * 128;

    const uint32_t aOff = ((wy * 32 + (lane & 15)) * 40 + ((lane >> 4) << 3)) * 2;
    const uint32_t bOff =
        ((wx * 64 + ((lane >> 4) << 3) + (lane & 7)) * 40 + (lane & 8)) * 2;

    float acc[2][8][4];
#pragma unroll
    for (int i = 0; i < 2; i++)
#pragma unroll
        for (int j = 0; j < 8; j++)
#pragma unroll
            for (int q = 0; q < 4; q++) acc[i][j][q] = 0.f;

#define FILL_H(kk, st)                                                          \
    {                                                                           \
        uint32_t stb = sb + (uint32_t)(st)*QSTAGE;                              \
        _Pragma("unroll") for (int i = 0; i < 2; i++)                           \
        {                                                                       \
            int s = tid + i * 256;                                              \
            int r = s >> 2, c = s & 3;                                          \
            uint32_t off = (uint32_t)(r * 40 + c * 8) * 2;                      \
            const __half* a0 = A + (size_t)(row0 + r) * 512 + (kk)*64 + c * 8;  \
            const __half* b0 = B + (size_t)(col0 + r) * 512 + (kk)*64 + c * 8;  \
            CP16(stb + off, a0);                                                \
            CP16(stb + PANEL + off, a0 + 32);                                   \
            CP16(stb + 2 * PANEL + off, b0);                                    \
            CP16(stb + 3 * PANEL + off, b0 + 32);                               \
        }                                                                       \
        CP_COMMIT();                                                            \
    }

    FILL_H(0, 0);
    FILL_H(1, 1);
    for (int kk = 0; kk < 8; kk++) {
        if (kk < 7) CP_WAIT(1); else CP_WAIT(0);
        __syncthreads();
        uint32_t stb = sb + (uint32_t)(kk & 1) * QSTAGE;
#pragma unroll
        for (int sub = 0; sub < 2; sub++) {
            uint32_t ap = stb + sub * PANEL;
            uint32_t bp = stb + (2 + sub) * PANEL;
#pragma unroll
            for (int ks = 0; ks < 2; ks++) {
                uint32_t af[2][4];
#pragma unroll
                for (int mi = 0; mi < 2; mi++)
                    ldsm4(af[mi], ap + aOff + mi * 1280 + ks * 32);
#pragma unroll
                for (int ng = 0; ng < 4; ng++) {
                    uint32_t bfr[4];
                    ldsm4(bfr, bp + bOff + ng * 1280 + ks * 32);
#pragma unroll
                    for (int mi = 0; mi < 2; mi++)
#pragma unroll
                        for (int p = 0; p < 2; p++)
                            mma_f16(acc[mi][ng * 2 + p], af[mi],
                                    bfr[p * 2], bfr[p * 2 + 1]);
                }
            }
        }
        __syncthreads();
        if (kk + 2 < 8) FILL_H(kk + 2, kk & 1);
    }

#pragma unroll
    for (int mi = 0; mi < 2; mi++)
#pragma unroll
        for (int ni = 0; ni < 8; ni++) {
            int r0 = row0 + wy * 32 + mi * 16 + (lane >> 2);
            int cc = col0 + wx * 64 + ni * 8 + (lane & 3) * 2;
            float b0 = __ldg(&bias[cc]), b1 = __ldg(&bias[cc + 1]);
#pragma unroll
            for (int half = 0; half < 2; half++) {
                int r = r0 + half * 8;
                float v0 = acc[mi][ni][half * 2] + b0;
                float v1 = acc[mi][ni][half * 2 + 1] + b1;
                if (MODE == 1) {
                    *(float2*)(Y + (size_t)r * 512 + cc) = make_float2(v0, v1);
                } else {
                    int bh = ((r >> 9) << 3) + (cc >> 6), l = r & 511, d = cc & 63;
                    *(float2*)(g_Vh + ((size_t)bh * 512 + l) * 64 + d) =
                        make_float2(v0, v1);
                }
            }
        }
}

// ---------------------------------------------------------------------------
// V transpose: g_Vh [bh][512][64] fp32 -> g_Vth [bh][64][512] fp16
// ---------------------------------------------------------------------------
__global__ __launch_bounds__(256) void vtrans()
{
    int l0 = blockIdx.x * 64, bh = blockIdx.y;
    __shared__ float sm[64][68];
    const float* V = g_Vh + (size_t)bh * 512 * 64;
    int tid = threadIdx.x;
#pragma unroll
    for (int i = 0; i < 4; i++) {
        int idx4 = tid + i * 256;
        int r = idx4 >> 4, c4 = (idx4 & 15) * 4;
        *(float4*)&sm[r][c4] = *(const float4*)(V + (size_t)(l0 + r) * 64 + c4);
    }
    __syncthreads();
    __half* O = g_Vth + (size_t)bh * 64 * 512;
#pragma unroll
    for (int i = 0; i < 16; i++) {
        int e = tid + i * 256;
        int d = e >> 6, l = e & 63;
        O[(size_t)d * 512 + l0 + l] = __float2half(sm[l][d]);
    }
}

// ---------------------------------------------------------------------------
// qk: S = Qs @ Ks^T per bh (bf16 3-term). 256 threads / 8 warps (2 my x 4 nx),
// warp tile 64x32, whole split-K resident (8 panels x 10240 = 81920).
// __launch_bounds__(256,2) for 2 CTAs/SM.
// ---------------------------------------------------------------------------
__global__ __launch_bounds__(256, 2) void qk_mma()
{
    int tk = blockIdx.x, tq = blockIdx.y, bh = blockIdx.z;
    if (tk > tq) return;
    const bf16* Aq = g_Qs + (size_t)bh * 512 * 128;
    const bf16* Bk = g_Ks + (size_t)bh * 512 * 128;
    extern __shared__ char sm[];
    uint32_t sb = smem_u32(sm);
    const int tid = threadIdx.x, lane = tid & 31, wid = tid >> 5;
    const int wy = wid >> 2, wx = wid & 3;
    const int row0 = tq * 128, col0 = tk * 128;

    const uint32_t aOff = ((wy * 64 + (lane & 15)) * 40 + ((lane >> 4) << 3)) * 2;
    const uint32_t bOff =
        ((wx * 32 + ((lane >> 4) << 3) + (lane & 7)) * 40 + (lane & 8)) * 2;

#pragma unroll
    for (int p = 0; p < 4; p++) {  // p = part*2 + kchunk
        int part = p >> 1, kk = p & 1;
        int colb = part * 64 + kk * 32;
#pragma unroll
        for (int i = 0; i < 2; i++) {
            int s = tid + i * 256;
            int r = s >> 2, c = s & 3;
            uint32_t off = (uint32_t)(r * 40 + c * 8) * 2;
            CP16(sb + p * PANEL + off,
                 Aq + (size_t)(row0 + r) * 128 + colb + c * 8);
            CP16(sb + (4 + p) * PANEL + off,
                 Bk + (size_t)(col0 + r) * 128 + colb + c * 8);
        }
    }
    CP_COMMIT();

    float acc[4][4][4];
#pragma unroll
    for (int i = 0; i < 4; i++)
#pragma unroll
        for (int j = 0; j < 4; j++)
#pragma unroll
            for (int q = 0; q < 4; q++) acc[i][j][q] = 0.f;

    CP_WAIT(0);
    __syncthreads();

#pragma unroll
    for (int kk = 0; kk < 2; kk++) {
        uint32_t qh = sb + kk * PANEL, ql = sb + (2 + kk) * PANEL;
        uint32_t kh = sb + (4 + kk) * PANEL, kl = sb + (6 + kk) * PANEL;
#pragma unroll
        for (int ks = 0; ks < 2; ks++) {
            uint32_t ah[4][4], al[4][4];
#pragma unroll
            for (int mi = 0; mi < 4; mi++) {
                ldsm4(ah[mi], qh + aOff + mi * 1280 + ks * 32);
                ldsm4(al[mi], ql + aOff + mi * 1280 + ks * 32);
            }
#pragma unroll
            for (int ng = 0; ng < 2; ng++) {
                uint32_t bh[4], bl[4];
                ldsm4(bh, kh + bOff + ng * 1280 + ks * 32);
                ldsm4(bl, kl + bOff + ng * 1280 + ks * 32);
#pragma unroll
                for (int mi = 0; mi < 4; mi++)
#pragma unroll
                    for (int p = 0; p < 2; p++) {
                        float* d = acc[mi][ng * 2 + p];
                        mma_bf16(d, ah[mi], bh[p * 2], bh[p * 2 + 1]);
                        mma_bf16(d, al[mi], bh[p * 2], bh[p * 2 + 1]);
                        mma_bf16(d, ah[mi], bl[p * 2], bl[p * 2 + 1]);
                    }
            }
        }
    }

    float* Smat = g_S + (size_t)bh * 512 * 512;
#pragma unroll
    for (int mi = 0; mi < 4; mi++)
#pragma unroll
        for (int ni = 0; ni < 4; ni++) {
            int r = row0 + wy * 64 + mi * 16 + (lane >> 2);
            int cc = col0 + wx * 32 + ni * 8 + (lane & 3) * 2;
            *(float2*)(Smat + (size_t)r * 512 + cc) =
                make_float2(acc[mi][ni][0], acc[mi][ni][1]);
            *(float2*)(Smat + (size_t)(r + 8) * 512 + cc) =
                make_float2(acc[mi][ni][2], acc[mi][ni][3]);
        }
}

// ---------------------------------------------------------------------------
// Per-row cumsum + area softmax + fold; emits G fp16 up to tile bound.
// ---------------------------------------------------------------------------
__global__ __launch_bounds__(128) void area_softmax_kernel()
{
    __shared__ float Cb[4][516];
    __shared__ float Tb[4][516];
    __shared__ float Ub[4][516];
    __shared__ float Vb[4][516];

    int wrp = threadIdx.x >> 5;
    int lane = threadIdx.x & 31;
    int t = blockIdx.x * 4 + wrp;
    int bh = blockIdx.y;
    int bound = ((t >> 7) + 1) << 7;  // av reads j < bound only

    const float* Srow = g_S + ((size_t)bh * L_ + t) * L_;
    __half* Grow = g_Gh + ((size_t)bh * L_ + t) * 512;
    float* C = Cb[wrp];
    float* T = Tb[wrp];
    float* U = Ub[wrp];
    float* V = Vb[wrp];

    if (lane == 0) C[0] = 0.f;
    float carry = 0.f;
    int nchunk = (t + 32) >> 5;
    for (int c0 = 0; c0 < nchunk; c0++) {
        int j = c0 * 32 + lane;
        float s = (j <= t) ? Srow[j] : 0.f;
#pragma unroll
        for (int off = 1; off < 32; off <<= 1) {
            float y = __shfl_up_sync(0xffffffffu, s, off);
            if (lane >= off) s += y;
        }
        s += carry;
        C[1 + j] = s;
        carry = __shfl_sync(0xffffffffu, s, 31);
    }
    __syncwarp();

    float m = -1e30f;
    for (int e = lane; e <= t; e += 32) {
        float ce = C[1 + e];
        m = fmaxf(m, ce - C[e]);
        if (e >= 1) m = fmaxf(m, (ce - C[e - 1]) * 0.5f);
        if (e >= 2) m = fmaxf(m, (ce - C[e - 2]) * (1.f / 3.f));
    }
#pragma unroll
    for (int off = 16; off; off >>= 1) m = fmaxf(m, __shfl_xor_sync(0xffffffffu, m, off));

    for (int e = t + 1 + lane; e < bound + 2; e += 32) {
        T[e] = 0.f; U[e] = 0.f; V[e] = 0.f;
    }

    float sum = 0.f;
    for (int e = lane; e <= t; e += 32) {
        float ce = C[1 + e];
        float p1 = __expf(ce - C[e] - m);
        float p2 = (e >= 1) ? __expf((ce - C[e - 1]) * 0.5f - m) : 0.f;
        float p3 = (e >= 2) ? __expf((ce - C[e - 2]) * (1.f / 3.f) - m) : 0.f;
        T[e] = p1 + p2 + p3;
        U[e] = p2 + p3;
        V[e] = p3;
        sum += p1 + p2 + p3;
    }
#pragma unroll
    for (int off = 16; off; off >>= 1) sum += __shfl_xor_sync(0xffffffffu, sum, off);
    float inv = 1.f / sum;
    __syncwarp();

    for (int j = lane; j < bound; j += 32) {
        float g = (j <= t) ? (T[j] + U[j + 1] + V[j + 2]) * inv : 0.f;
        Grow[j] = __float2half(g);
    }
}

// ---------------------------------------------------------------------------
// av: attn = G @ Vt^T per bh, fp16 single-term. 128(M)x64(N), 4 warps, tri skip.
// ---------------------------------------------------------------------------
__global__ __launch_bounds__(128) void av_h()
{
    int tm = blockIdx.x, bh = blockIdx.y;
    const __half* A = g_Gh + (size_t)bh * 512 * 512;
    const __half* Bp = g_Vth + (size_t)bh * 64 * 512;
    __shared__ __half sA[2][128 * 40];
    __shared__ __half sB[2][64 * 40];
    const int tid = threadIdx.x, lane = tid & 31, wy = tid >> 5;
    const int row0 = tm * 128;
    const int rA = tid >> 2, cA = (tid & 3) * 8;

    uint32_t sAu = smem_u32(sA), sBu = smem_u32(sB);
    uint32_t aBase = sAu + (((wy * 32 + (lane & 15)) * 40 + ((lane >> 4) << 3)) << 1);
    uint32_t bBase = sBu + (((((lane >> 4) << 3) + (lane & 7)) * 40 + (lane & 8)) << 1);

    float acc[2][8][4];
#pragma unroll
    for (int i = 0; i < 2; i++)
#pragma unroll
        for (int j = 0; j < 8; j++)
#pragma unroll
            for (int q = 0; q < 4; q++) acc[i][j][q] = 0.f;

    uint4 pa[4], pb[2];
#define LDT_H(jc)                                                                   \
    {                                                                               \
        _Pragma("unroll") for (int i = 0; i < 4; i++)                               \
            pa[i] = *(const uint4*)(A + (size_t)(row0 + rA + i * 32) * 512 +        \
                                    (jc)*32 + cA);                                  \
        _Pragma("unroll") for (int i = 0; i < 2; i++)                               \
            pb[i] = *(const uint4*)(Bp + (size_t)(rA + i * 32) * 512 + (jc)*32 + cA); \
    }
#define STT_H(b)                                                                    \
    {                                                                               \
        _Pragma("unroll") for (int i = 0; i < 4; i++)                               \
            *(uint4*)&sA[b][(rA + i * 32) * 40 + cA] = pa[i];                       \
        _Pragma("unroll") for (int i = 0; i < 2; i++)                               \
            *(uint4*)&sB[b][(rA + i * 32) * 40 + cA] = pb[i];                       \
    }

    int nj = (tm + 1) * 4;
    LDT_H(0); STT_H(0); __syncthreads();
    for (int it = 0; it < nj; it++) {
        int b = it & 1;
        if (it < nj - 1) LDT_H(it + 1);
        uint32_t af[2][2][4], bfr[4][2][4];
        uint32_t aB = aBase + b * 10240, bB = bBase + b * 5120;
#pragma unroll
        for (int mi = 0; mi < 2; mi++)
#pragma unroll
            for (int ks = 0; ks < 2; ks++) ldsm4(af[mi][ks], aB + mi * 1280 + ks * 32);
#pragma unroll
        for (int ng = 0; ng < 4; ng++)
#pragma unroll
            for (int ks = 0; ks < 2; ks++) ldsm4(bfr[ng][ks], bB + ng * 1280 + ks * 32);
#pragma unroll
        for (int ks = 0; ks < 2; ks++)
#pragma unroll
            for (int mi = 0; mi < 2; mi++)
#pragma unroll
                for (int ni = 0; ni < 8; ni++)
                    mma_f16(acc[mi][ni], af[mi][ks],
                            bfr[ni >> 1][ks][(ni & 1) * 2],
                            bfr[ni >> 1][ks][(ni & 1) * 2 + 1]);
        if (it < nj - 1) { STT_H(b ^ 1); __syncthreads(); }
    }

    int b_ = bh >> 3, h_ = bh & 7;
#pragma unroll
    for (int mi = 0; mi < 2; mi++)
#pragma unroll
        for (int ni = 0; ni < 8; ni++) {
            int t0 = row0 + wy * 32 + mi * 16 + (lane >> 2);
            int d = ni * 8 + (lane & 3) * 2;
#pragma unroll
            for (int half = 0; half < 2; half++) {
                int t = t0 + half * 8;
                __half2 hv = __floats2half2_rn(acc[mi][ni][half * 2],
                                               acc[mi][ni][half * 2 + 1]);
                *(__half2*)(g_Aath + ((size_t)(b_ * 512 + t)) * 512 + h_ * 64 + d) = hv;
            }
        }
}

// ---------------------------------------------------------------------------
extern "C" void kernel_launch(void* const* d_in, const int* in_sizes, int n_in,
                              void* d_out, int out_size)
{
    const float* q  = (const float*)d_in[0];
    const float* k  = (const float*)d_in[1];
    const float* v  = (const float*)d_in[2];
    // d_in[3] = attn_mask — analytic (area end <= t), unused.
    const float* Wq = (const float*)d_in[4];
    const float* bq = (const float*)d_in[5];
    const float* Wk = (const float*)d_in[6];
    const float* bk = (const float*)d_in[7];
    const float* Wv = (const float*)d_in[8];
    const float* bv = (const float*)d_in[9];
    const float* Wo = (const float*)d_in[10];
    const float* bo = (const float*)d_in[11];
    float* out = (float*)d_out;

    cudaFuncSetAttribute(mma_gemm<0>, cudaFuncAttributeMaxDynamicSharedMemorySize, QSMEM);
    cudaFuncSetAttribute(mma_gemm<1>, cudaFuncAttributeMaxDynamicSharedMemorySize, QSMEM);
    cudaFuncSetAttribute(gemm_h<0>, cudaFuncAttributeMaxDynamicSharedMemorySize, QSMEM);
    cudaFuncSetAttribute(gemm_h<1>, cudaFuncAttributeMaxDynamicSharedMemorySize, QSMEM);
    cudaFuncSetAttribute(qk_mma, cudaFuncAttributeMaxDynamicSharedMemorySize, 81920);

    convW_all<<<dim3(16, 16, 4), 256>>>(Wq, Wk, Wv, Wo);
    convX_all<<<dim3(4096, 1, 2), 256>>>(q, k);
    convV_h<<<4096, 256>>>(v);

    dim3 gG(4, 64);
    mma_gemm<0><<<gG, 256, QSMEM>>>(bq);
    mma_gemm<1><<<gG, 256, QSMEM>>>(bk);
    gemm_h<0><<<gG, 256, QSMEM>>>(bv, nullptr);

    vtrans<<<dim3(8, 128), 256>>>();
    qk_mma<<<dim3(4, 4, 128), 256, 81920>>>();
    area_softmax_kernel<<<dim3(128, 128), 128>>>();
    av_h<<<dim3(4, 128), 128>>>();

    gemm_h<1><<<gG, 256, QSMEM>>>(bo, out);
}